// round 1
// baseline (speedup 1.0000x reference)
#include <cuda_runtime.h>
#include <math.h>

#define T_STEPS 10
#define B_GR    8
#define NPG     1080
#define N_NODES 8640
#define TN      86400            // T_STEPS * N_NODES
#define DEG     16
#define E_EDGES 138240

// ---------------- scratch (device globals; no allocation allowed) ----------------
__device__ float g_bufA[(size_t)TN * 512];
__device__ float g_bufB[(size_t)TN * 512];
__device__ float g_es[TN * 8];
__device__ float g_ed[TN * 8];
__device__ float g_emb[T_STEPS * B_GR * 8];
__device__ float g_uv[32];

// ---------------- layer 1 helpers (aggregate in input space, K=2) ----------------
// uv[0..15]  = us[h][f] = sum_c W1[f,h*64+c]*as1[h,c]
// uv[16..31] = ud[h][f]
__global__ void uvec_l1(const float* __restrict__ W1, const float* __restrict__ as1,
                        const float* __restrict__ ad1) {
    int tid = threadIdx.x;
    if (tid < 32) {
        int d = tid >> 4;
        int h = (tid >> 1) & 7;
        int f = tid & 1;
        const float* a = d ? ad1 : as1;
        float s = 0.f;
        #pragma unroll
        for (int c = 0; c < 64; c++) s += W1[f * 512 + h * 64 + c] * a[h * 64 + c];
        g_uv[tid] = s;
    }
}

__global__ void esed_l1(const float* __restrict__ x) {
    int idx = blockIdx.x * blockDim.x + threadIdx.x;   // TN*8
    if (idx >= TN * 8) return;
    int row = idx >> 3, h = idx & 7;
    float x0 = x[row * 2], x1 = x[row * 2 + 1];
    g_es[idx] = x0 * g_uv[h * 2]      + x1 * g_uv[h * 2 + 1];
    g_ed[idx] = x0 * g_uv[16 + h * 2] + x1 * g_uv[16 + h * 2 + 1];
}

__global__ void gat_agg_l1(const float* __restrict__ x, const int* __restrict__ src,
                           const float* __restrict__ W1, const float* __restrict__ b1,
                           float* __restrict__ Xout) {
    __shared__ int   rows[17];
    __shared__ float ew[17 * 8];
    __shared__ float alpha[17 * 8];
    __shared__ float z[8][2];
    int blk = blockIdx.x;                 // == t*N_NODES + n
    int n = blk % N_NODES;
    int tbase = blk - n;                  // t*N_NODES
    int tid = threadIdx.x;
    if (tid < 16) rows[tid] = tbase + src[n * 16 + tid];
    else if (tid == 16) rows[16] = blk;
    __syncthreads();
    for (int idx = tid; idx < 136; idx += blockDim.x) {
        int k = idx >> 3, h = idx & 7;
        float e = g_es[rows[k] * 8 + h] + g_ed[blk * 8 + h];
        ew[idx] = e >= 0.f ? e : 0.2f * e;
    }
    __syncthreads();
    if (tid < 8) {
        float m = -1e30f;
        #pragma unroll
        for (int k = 0; k < 17; k++) m = fmaxf(m, ew[k * 8 + tid]);
        float s = 0.f;
        #pragma unroll
        for (int k = 0; k < 17; k++) { float v = expf(ew[k * 8 + tid] - m); alpha[k * 8 + tid] = v; s += v; }
        float inv = 1.f / (s + 1e-16f);
        #pragma unroll
        for (int k = 0; k < 17; k++) alpha[k * 8 + tid] *= inv;
    }
    __syncthreads();
    if (tid < 16) {
        int h = tid >> 1, f = tid & 1;
        float a = 0.f;
        #pragma unroll
        for (int k = 0; k < 17; k++) a += alpha[k * 8 + h] * x[rows[k] * 2 + f];
        z[h][f] = a;
    }
    __syncthreads();
    for (int j = tid; j < 512; j += blockDim.x) {
        int h = j >> 6;
        float v = z[h][0] * W1[j] + z[h][1] * W1[512 + j] + b1[j];
        Xout[(size_t)blk * 512 + j] = v > 0.f ? v : (expf(v) - 1.f);
    }
}

// ---------------- generic 64x64 fp32 GEMM: C[M,Nc] = A[M,K] @ W[K,Nc] ----------------
// requires M%64==0, Nc%64==0, K%16==0
__global__ void gemm64(const float* __restrict__ A, const float* __restrict__ W,
                       float* __restrict__ C, int M, int K, int Nc) {
    __shared__ float As[16][68];   // transposed: As[k][row]
    __shared__ float Ws[16][68];
    const int tid = threadIdx.x;
    const int tx = tid & 15, ty = tid >> 4;
    const int rb = blockIdx.y * 64;
    const int cb = blockIdx.x * 64;
    const int arow = tid >> 2, akq = tid & 3;
    const int wk = tid >> 4, wc4 = tid & 15;
    float acc[4][4] = {};
    for (int k0 = 0; k0 < K; k0 += 16) {
        float4 av = *(const float4*)(A + (size_t)(rb + arow) * K + k0 + akq * 4);
        float4 wv = *(const float4*)(W + (size_t)(k0 + wk) * Nc + cb + wc4 * 4);
        __syncthreads();
        As[akq * 4 + 0][arow] = av.x;
        As[akq * 4 + 1][arow] = av.y;
        As[akq * 4 + 2][arow] = av.z;
        As[akq * 4 + 3][arow] = av.w;
        *(float4*)&Ws[wk][wc4 * 4] = wv;
        __syncthreads();
        #pragma unroll
        for (int k = 0; k < 16; k++) {
            float4 a = *(const float4*)&As[k][ty * 4];
            float4 b = *(const float4*)&Ws[k][tx * 4];
            acc[0][0] += a.x * b.x; acc[0][1] += a.x * b.y; acc[0][2] += a.x * b.z; acc[0][3] += a.x * b.w;
            acc[1][0] += a.y * b.x; acc[1][1] += a.y * b.y; acc[1][2] += a.y * b.z; acc[1][3] += a.y * b.w;
            acc[2][0] += a.z * b.x; acc[2][1] += a.z * b.y; acc[2][2] += a.z * b.z; acc[2][3] += a.z * b.w;
            acc[3][0] += a.w * b.x; acc[3][1] += a.w * b.y; acc[3][2] += a.w * b.z; acc[3][3] += a.w * b.w;
        }
    }
    #pragma unroll
    for (int i = 0; i < 4; i++) {
        float4 v = make_float4(acc[i][0], acc[i][1], acc[i][2], acc[i][3]);
        *(float4*)(C + (size_t)(rb + ty * 4 + i) * Nc + cb + tx * 4) = v;
    }
}

// ---------------- L4 GEMM: K=128, Nc=8 ----------------
__global__ void gemm_l4(const float* __restrict__ X, const float* __restrict__ W4,
                        float* __restrict__ Y) {
    int idx = blockIdx.x * blockDim.x + threadIdx.x;   // TN*8
    if (idx >= TN * 8) return;
    int row = idx >> 3, j = idx & 7;
    const float* xr = X + (size_t)row * 128;
    float acc = 0.f;
    #pragma unroll 8
    for (int k = 0; k < 128; k++) acc += xr[k] * W4[k * 8 + j];
    Y[idx] = acc;
}

// ---------------- generic attention coefficients ----------------
template<int H, int C>
__global__ void attn_coef(const float* __restrict__ Y, const float* __restrict__ as_,
                          const float* __restrict__ ad_) {
    int idx = blockIdx.x * blockDim.x + threadIdx.x;   // TN*H
    if (idx >= TN * H) return;
    int row = idx / H, h = idx % H;
    const float* y = Y + (size_t)row * (H * C) + h * C;
    const float* a = as_ + h * C;
    const float* d = ad_ + h * C;
    float se = 0.f, de = 0.f;
    #pragma unroll 8
    for (int c = 0; c < C; c++) { float v = y[c]; se += v * a[c]; de += v * d[c]; }
    g_es[idx] = se;
    g_ed[idx] = de;
}

// ---------------- generic GAT aggregation (+bias +ELU) ----------------
template<int H, int C>
__global__ void gat_agg(const float* __restrict__ Y, const int* __restrict__ src,
                        const float* __restrict__ bias, float* __restrict__ Xout) {
    constexpr int HC = H * C;
    __shared__ int   rows[17];
    __shared__ float ew[17 * H];
    __shared__ float alpha[17 * H];
    int blk = blockIdx.x;                 // t*N_NODES + n
    int n = blk % N_NODES;
    int tbase = blk - n;
    int tid = threadIdx.x;
    if (tid < 16) rows[tid] = tbase + src[n * 16 + tid];
    else if (tid == 16) rows[16] = blk;
    __syncthreads();
    for (int idx = tid; idx < 17 * H; idx += blockDim.x) {
        int k = idx / H, h = idx % H;
        float e = g_es[rows[k] * H + h] + g_ed[blk * H + h];
        ew[idx] = e >= 0.f ? e : 0.2f * e;
    }
    __syncthreads();
    if (tid < H) {
        float m = -1e30f;
        #pragma unroll
        for (int k = 0; k < 17; k++) m = fmaxf(m, ew[k * H + tid]);
        float s = 0.f;
        #pragma unroll
        for (int k = 0; k < 17; k++) { float v = expf(ew[k * H + tid] - m); alpha[k * H + tid] = v; s += v; }
        float inv = 1.f / (s + 1e-16f);
        #pragma unroll
        for (int k = 0; k < 17; k++) alpha[k * H + tid] *= inv;
    }
    __syncthreads();
    for (int j = tid; j < HC; j += blockDim.x) {
        int h = j / C;
        float acc = 0.f;
        #pragma unroll
        for (int k = 0; k < 17; k++) acc += alpha[k * H + h] * Y[(size_t)rows[k] * HC + j];
        float v = acc + bias[j];
        Xout[(size_t)blk * HC + j] = v > 0.f ? v : (expf(v) - 1.f);
    }
}

// ---------------- mean pool over each graph's 1080 nodes ----------------
__global__ void pool_kernel(const float* __restrict__ X4) {
    int tb = blockIdx.x;                 // t*B_GR + b
    int t = tb / B_GR, b = tb % B_GR;
    int tid = threadIdx.x;
    float acc[8] = {};
    for (int nn = tid; nn < NPG; nn += blockDim.x) {
        const float* p = X4 + ((size_t)(t * N_NODES + b * NPG + nn)) * 8;
        #pragma unroll
        for (int f = 0; f < 8; f++) acc[f] += p[f];
    }
    __shared__ float s[8];
    if (tid < 8) s[tid] = 0.f;
    __syncthreads();
    #pragma unroll
    for (int f = 0; f < 8; f++) atomicAdd(&s[f], acc[f]);
    __syncthreads();
    if (tid < 8) g_emb[tb * 8 + tid] = s[tid] * (1.0f / (float)NPG);
}

// ---------------- LSTM (T steps) + final FC ----------------
__device__ __forceinline__ float sigmoidf(float x) { return 1.f / (1.f + expf(-x)); }

__global__ void lstm_fc(const float* __restrict__ w_ih, const float* __restrict__ w_hh,
                        const float* __restrict__ b_ih, const float* __restrict__ b_hh,
                        const float* __restrict__ w_fc, const float* __restrict__ b_fc,
                        float* __restrict__ out) {
    __shared__ float h[8][128], c[8][128], g[8][512], xs[8][8];
    int tid = threadIdx.x;   // 1024 threads
    for (int i = tid; i < 8 * 128; i += 1024) { ((float*)h)[i] = 0.f; ((float*)c)[i] = 0.f; }
    __syncthreads();
    for (int t = 0; t < T_STEPS; t++) {
        if (tid < 64) xs[tid >> 3][tid & 7] = g_emb[t * 64 + tid];
        __syncthreads();
        #pragma unroll
        for (int task = tid; task < 4096; task += 1024) {
            int b = task >> 9, row = task & 511;
            float acc = b_ih[row] + b_hh[row];
            const float* wi = w_ih + row * 8;
            #pragma unroll
            for (int k = 0; k < 8; k++) acc += xs[b][k] * wi[k];
            const float* wh = w_hh + row * 128;
            #pragma unroll 8
            for (int j = 0; j < 128; j++) acc += h[b][j] * wh[j];
            g[b][row] = acc;
        }
        __syncthreads();
        if (tid < 1024) {
            int b = tid >> 7, u = tid & 127;
            float ig = sigmoidf(g[b][u]);
            float fg = sigmoidf(g[b][128 + u]);
            float gg = tanhf(g[b][256 + u]);
            float og = sigmoidf(g[b][384 + u]);
            float cn = fg * c[b][u] + ig * gg;
            c[b][u] = cn;
            h[b][u] = og * tanhf(cn);
        }
        __syncthreads();
    }
    if (tid < 16) {
        int b = tid >> 1, o = tid & 1;
        float acc = b_fc[o];
        const float* w = w_fc + o * 128;
        #pragma unroll 8
        for (int j = 0; j < 128; j++) acc += h[b][j] * w[j];
        out[b * 2 + o] = acc;
    }
}

// ---------------- host launch ----------------
extern "C" void kernel_launch(void* const* d_in, const int* in_sizes, int n_in,
                              void* d_out, int out_size) {
    const float *x_seq = 0, *W1 = 0, *as1 = 0, *ad1 = 0, *b1 = 0;
    const float *W2 = 0, *as2 = 0, *ad2 = 0, *b2 = 0;
    const float *W3 = 0, *as3 = 0, *ad3 = 0, *b3 = 0;
    const float *W4 = 0, *as4 = 0, *ad4 = 0, *b4 = 0;
    const float *w_ih = 0, *w_hh = 0, *b_ih = 0, *b_hh = 0, *w_fc = 0, *b_fc = 0;
    const int *edge = 0;
    int c1024 = 0, c512 = 0, c256 = 0, c128 = 0, c8 = 0;
    for (int i = 0; i < n_in; i++) {
        const float* p = (const float*)d_in[i];
        switch (in_sizes[i]) {
            case 172800: x_seq = p; break;
            case 276480: edge = (const int*)p; break;
            case 8640:   /* batch, unused */ break;
            case 131072: W2 = p; break;
            case 65536:  w_hh = p; break;
            case 32768:  W3 = p; break;
            case 4096:   w_ih = p; break;
            case 1024:   { if (c1024++ == 0) W1 = p; else W4 = p; } break;
            case 512: { int k = c512++;
                if (k == 0) as1 = p; else if (k == 1) ad1 = p; else if (k == 2) b1 = p;
                else if (k == 3) b_ih = p; else b_hh = p; } break;
            case 256: { int k = c256++;
                if (k == 0) as2 = p; else if (k == 1) ad2 = p; else if (k == 2) b2 = p;
                else w_fc = p; } break;
            case 128: { int k = c128++;
                if (k == 0) as3 = p; else if (k == 1) ad3 = p; else b3 = p; } break;
            case 8: { int k = c8++;
                if (k == 0) as4 = p; else if (k == 1) ad4 = p; else b4 = p; } break;
            case 2: b_fc = p; break;
            default: break;
        }
    }
    const int* src = edge;   // edge_index[0] = first E_EDGES ints

    float *bufA, *bufB;
    cudaGetSymbolAddress((void**)&bufA, g_bufA);
    cudaGetSymbolAddress((void**)&bufB, g_bufB);

    // ---- Layer 1 (aggregate in input space; K=2) ----
    uvec_l1<<<1, 32>>>(W1, as1, ad1);
    esed_l1<<<(TN * 8 + 255) / 256, 256>>>(x_seq);
    gat_agg_l1<<<TN, 256>>>(x_seq, src, W1, b1, bufB);

    // ---- Layer 2: [TN,512] @ [512,256] ----
    gemm64<<<dim3(256 / 64, TN / 64), 256>>>(bufB, W2, bufA, TN, 512, 256);
    attn_coef<8, 32><<<(TN * 8 + 255) / 256, 256>>>(bufA, as2, ad2);
    gat_agg<8, 32><<<TN, 256>>>(bufA, src, b2, bufB);

    // ---- Layer 3: [TN,256] @ [256,128] ----
    gemm64<<<dim3(128 / 64, TN / 64), 256>>>(bufB, W3, bufA, TN, 256, 128);
    attn_coef<8, 16><<<(TN * 8 + 255) / 256, 256>>>(bufA, as3, ad3);
    gat_agg<8, 16><<<TN, 128>>>(bufA, src, b3, bufB);

    // ---- Layer 4: [TN,128] @ [128,8] ----
    gemm_l4<<<(TN * 8 + 255) / 256, 256>>>(bufB, W4, bufA);
    attn_coef<1, 8><<<(TN + 255) / 256, 256>>>(bufA, as4, ad4);
    gat_agg<1, 8><<<TN, 32>>>(bufA, src, b4, bufB);

    // ---- pool + LSTM + FC ----
    pool_kernel<<<T_STEPS * B_GR, 256>>>(bufB);
    lstm_fc<<<1, 1024>>>(w_ih, w_hh, b_ih, b_hh, w_fc, b_fc, (float*)d_out);
}

// round 2
// speedup vs baseline: 1.0084x; 1.0084x over previous
#include <cuda_runtime.h>
#include <math.h>

#define T_STEPS 10
#define B_GR    8
#define NPG     1080
#define N_NODES 8640
#define TN      86400
#define DEG     16

// ---------------- scratch ----------------
__device__ float g_bufA[(size_t)TN * 256];   // gemm outputs (max 256 wide)
__device__ float g_bufB[(size_t)TN * 512];   // activations (max 512 wide)
__device__ float g_es[TN * 8];
__device__ float g_ed[TN * 8];
__device__ float g_alpha[(size_t)TN * 8 * 17];
__device__ float g_z[TN * 16];
__device__ float g_emb[T_STEPS * B_GR * 8];
__device__ float g_uv[32];

// ---------------- fast exp for x <= 0 (FMA pipe only, no MUFU) ----------------
__device__ __forceinline__ float exp_neg(float x) {
    x = fmaxf(x, -87.0f);
    const float L2E = 1.4426950408889634f;
    float z = fmaf(x, L2E, 12582912.0f);      // round-to-nearest integer in mantissa
    int   ei = __float_as_int(z);
    float n = z - 12582912.0f;
    float f = fmaf(x, L2E, -n);               // f in [-0.5, 0.5]
    float r = fmaf(1.5403530e-4f, f, 1.3333558e-3f);
    r = fmaf(r, f, 9.6181291e-3f);
    r = fmaf(r, f, 5.5504109e-2f);
    r = fmaf(r, f, 2.4022651e-1f);
    r = fmaf(r, f, 6.9314718e-1f);
    r = fmaf(r, f, 1.0f);
    float s = __int_as_float((ei + 127) << 23);   // 2^n  (n in [-126, 0])
    return r * s;
}

__device__ __forceinline__ float elu_f(float v) {
    return v > 0.f ? v : exp_neg(v) - 1.f;
}

// ---------------- layer 1: fold W1 into attention vectors ----------------
__global__ void uvec_l1(const float* __restrict__ W1, const float* __restrict__ as1,
                        const float* __restrict__ ad1) {
    int tid = threadIdx.x;
    if (tid < 32) {
        int d = tid >> 4, h = (tid >> 1) & 7, f = tid & 1;
        const float* a = d ? ad1 : as1;
        float s = 0.f;
        #pragma unroll
        for (int c = 0; c < 64; c++) s += W1[f * 512 + h * 64 + c] * a[h * 64 + c];
        g_uv[tid] = s;
    }
}

__global__ void esed_l1(const float* __restrict__ x) {
    int idx = blockIdx.x * blockDim.x + threadIdx.x;
    if (idx >= TN * 8) return;
    int row = idx >> 3, h = idx & 7;
    float x0 = x[row * 2], x1 = x[row * 2 + 1];
    g_es[idx] = x0 * g_uv[h * 2]      + x1 * g_uv[h * 2 + 1];
    g_ed[idx] = x0 * g_uv[16 + h * 2] + x1 * g_uv[16 + h * 2 + 1];
}

// ---------------- attention alpha precompute (17-way softmax per node,head) ----------------
// grid: T*B*8 (chunks of 135 nodes), dynamic smem: es tile + local src
template<int H>
__global__ void alpha_kernel(const int* __restrict__ src) {
    extern __shared__ float sm[];
    float* es_s = sm;                       // NPG*H
    int*   lsrc = (int*)(sm + NPG * H);     // 135*16
    int blk = blockIdx.x;
    int chunk = blk & 7;
    int tb = blk >> 3;
    int b = tb & 7;
    int t = tb >> 3;
    int base = t * N_NODES + b * NPG;
    int tid = threadIdx.x;
    for (int i = tid; i < NPG * H; i += blockDim.x)
        es_s[i] = g_es[(size_t)base * H + i];
    int n0 = chunk * 135;
    for (int i = tid; i < 135 * 16; i += blockDim.x)
        lsrc[i] = src[(size_t)(b * NPG + n0) * 16 + i] - b * NPG;
    __syncthreads();
    for (int task = tid; task < 135 * H; task += blockDim.x) {
        int nl = task / H, h = task % H;
        int n = n0 + nl;
        float ed = g_ed[(size_t)(base + n) * H + h];
        float ev[17];
        float m = -1e30f;
        #pragma unroll
        for (int k = 0; k < 16; k++) {
            float e = es_s[lsrc[nl * 16 + k] * H + h] + ed;
            e = e >= 0.f ? e : 0.2f * e;
            ev[k] = e; m = fmaxf(m, e);
        }
        {
            float e = es_s[n * H + h] + ed;
            e = e >= 0.f ? e : 0.2f * e;
            ev[16] = e; m = fmaxf(m, e);
        }
        float s = 0.f;
        #pragma unroll
        for (int k = 0; k < 17; k++) { float v = exp_neg(ev[k] - m); ev[k] = v; s += v; }
        float inv = 1.f / (s + 1e-16f);
        float* ap = g_alpha + ((size_t)(base + n) * H + h) * 17;
        #pragma unroll
        for (int k = 0; k < 17; k++) ap[k] = ev[k] * inv;
    }
}

// ---------------- layer-1 aggregation into z[TN,16] ----------------
__global__ void z_agg(const float* __restrict__ x, const int* __restrict__ src) {
    __shared__ float xs[NPG * 2];
    __shared__ int lsrc[135 * 16];
    int blk = blockIdx.x;
    int chunk = blk & 7;
    int tb = blk >> 3;
    int b = tb & 7;
    int t = tb >> 3;
    int base = t * N_NODES + b * NPG;
    int tid = threadIdx.x;
    for (int i = tid; i < NPG * 2; i += blockDim.x) xs[i] = x[(size_t)base * 2 + i];
    int n0 = chunk * 135;
    for (int i = tid; i < 135 * 16; i += blockDim.x)
        lsrc[i] = src[(size_t)(b * NPG + n0) * 16 + i] - b * NPG;
    __syncthreads();
    for (int task = tid; task < 135 * 16; task += blockDim.x) {
        int nl = task >> 4, hf = task & 15;
        int h = hf >> 1, f = hf & 1;
        int n = n0 + nl;
        const float* ap = g_alpha + ((size_t)(base + n) * 8 + h) * 17;
        float acc = 0.f;
        #pragma unroll
        for (int k = 0; k < 16; k++) acc += ap[k] * xs[lsrc[nl * 16 + k] * 2 + f];
        acc += ap[16] * xs[n * 2 + f];
        g_z[(size_t)(base + n) * 16 + hf] = acc;
    }
}

// ---------------- layer-1 output: X1 = elu(z @ blockdiag(W1) + b1), [TN,512] ----------------
__global__ void l1_out(const float* __restrict__ W1, const float* __restrict__ b1,
                       float* __restrict__ X1) {
    int idx = blockIdx.x * blockDim.x + threadIdx.x;    // TN*128 quads
    if (idx >= TN * 128) return;
    int row = idx >> 7, q = idx & 127;
    int h = q >> 4;
    float z0 = g_z[(size_t)row * 16 + h * 2];
    float z1 = g_z[(size_t)row * 16 + h * 2 + 1];
    float4 w0 = *(const float4*)(W1 + q * 4);
    float4 w1 = *(const float4*)(W1 + 512 + q * 4);
    float4 bb = *(const float4*)(b1 + q * 4);
    float4 v;
    v.x = elu_f(fmaf(z0, w0.x, fmaf(z1, w1.x, bb.x)));
    v.y = elu_f(fmaf(z0, w0.y, fmaf(z1, w1.y, bb.y)));
    v.z = elu_f(fmaf(z0, w0.z, fmaf(z1, w1.z, bb.z)));
    v.w = elu_f(fmaf(z0, w0.w, fmaf(z1, w1.w, bb.w)));
    *(float4*)(X1 + (size_t)row * 512 + q * 4) = v;
}

// ---------------- 128x128 fp32 GEMM, 8x8 microtile: C = A[M,K] @ W[K,Nc] ----------------
__global__ __launch_bounds__(256, 2)
void gemm128(const float* __restrict__ A, const float* __restrict__ W,
             float* __restrict__ C, int M, int K, int Nc) {
    __shared__ float As[16][136];
    __shared__ float Ws[16][136];
    const int tid = threadIdx.x;
    const int tx = tid & 15, ty = tid >> 4;
    const int rb = blockIdx.y * 128, cb = blockIdx.x * 128;
    const int arow = tid >> 1, ap = tid & 1;
    const int wk = tid >> 5, wc = tid & 31;
    float acc[8][8] = {};
    for (int k0 = 0; k0 < K; k0 += 16) {
        const float* abase = A + (size_t)(rb + arow) * K + k0 + ap * 8;
        float4 av0 = *(const float4*)(abase);
        float4 av1 = *(const float4*)(abase + 4);
        float4 wv0 = *(const float4*)(W + (size_t)(k0 + wk) * Nc + cb + wc * 4);
        float4 wv1 = *(const float4*)(W + (size_t)(k0 + wk + 8) * Nc + cb + wc * 4);
        __syncthreads();
        As[ap * 8 + 0][arow] = av0.x; As[ap * 8 + 1][arow] = av0.y;
        As[ap * 8 + 2][arow] = av0.z; As[ap * 8 + 3][arow] = av0.w;
        As[ap * 8 + 4][arow] = av1.x; As[ap * 8 + 5][arow] = av1.y;
        As[ap * 8 + 6][arow] = av1.z; As[ap * 8 + 7][arow] = av1.w;
        *(float4*)&Ws[wk][wc * 4] = wv0;
        *(float4*)&Ws[wk + 8][wc * 4] = wv1;
        __syncthreads();
        #pragma unroll
        for (int k = 0; k < 16; k++) {
            float4 a0 = *(const float4*)&As[k][ty * 4];
            float4 a1 = *(const float4*)&As[k][64 + ty * 4];
            float4 b0 = *(const float4*)&Ws[k][tx * 4];
            float4 b1 = *(const float4*)&Ws[k][64 + tx * 4];
            float a[8] = {a0.x, a0.y, a0.z, a0.w, a1.x, a1.y, a1.z, a1.w};
            float bv[8] = {b0.x, b0.y, b0.z, b0.w, b1.x, b1.y, b1.z, b1.w};
            #pragma unroll
            for (int i = 0; i < 8; i++)
                #pragma unroll
                for (int j = 0; j < 8; j++)
                    acc[i][j] = fmaf(a[i], bv[j], acc[i][j]);
        }
    }
    #pragma unroll
    for (int i = 0; i < 8; i++) {
        int r = rb + ((i < 4) ? (ty * 4 + i) : (64 + ty * 4 + i - 4));
        float4 v0 = make_float4(acc[i][0], acc[i][1], acc[i][2], acc[i][3]);
        float4 v1 = make_float4(acc[i][4], acc[i][5], acc[i][6], acc[i][7]);
        *(float4*)(C + (size_t)r * Nc + cb + tx * 4) = v0;
        *(float4*)(C + (size_t)r * Nc + cb + 64 + tx * 4) = v1;
    }
}

// ---------------- small GEMM L4: [TN,128] @ [128,8] ----------------
__global__ void gemm_l4(const float* __restrict__ X, const float* __restrict__ W4,
                        float* __restrict__ Y) {
    int idx = blockIdx.x * blockDim.x + threadIdx.x;
    if (idx >= TN * 8) return;
    int row = idx >> 3, j = idx & 7;
    const float* xr = X + (size_t)row * 128;
    float acc = 0.f;
    #pragma unroll 8
    for (int k = 0; k < 128; k++) acc = fmaf(xr[k], W4[k * 8 + j], acc);
    Y[idx] = acc;
}

// ---------------- attention coefficients ----------------
template<int H, int C>
__global__ void attn_coef(const float* __restrict__ Y, const float* __restrict__ as_,
                          const float* __restrict__ ad_) {
    int idx = blockIdx.x * blockDim.x + threadIdx.x;
    if (idx >= TN * H) return;
    int row = idx / H, h = idx % H;
    const float* y = Y + (size_t)row * (H * C) + h * C;
    float se = 0.f, de = 0.f;
    #pragma unroll
    for (int c = 0; c < C; c += 4) {
        float4 v = *(const float4*)(y + c);
        float4 a = *(const float4*)(as_ + h * C + c);
        float4 d = *(const float4*)(ad_ + h * C + c);
        se += v.x * a.x + v.y * a.y + v.z * a.z + v.w * a.w;
        de += v.x * d.x + v.y * d.y + v.z * d.z + v.w * d.w;
    }
    g_es[idx] = se;
    g_ed[idx] = de;
}

// ---------------- graph-tiled GAT aggregation (+bias+ELU) ----------------
// grid: T*B*H blocks; dynamic smem: feature tile [NPG][C] + local src [NPG*16]
template<int H, int C>
__global__ void gat_agg(const float* __restrict__ Y, const int* __restrict__ src,
                        const float* __restrict__ bias, float* __restrict__ Xout) {
    extern __shared__ float sm[];
    float* tile = sm;                       // NPG*C
    int*   lsrc = (int*)(sm + NPG * C);     // NPG*16
    constexpr int HC = H * C;
    constexpr int Q = C / 4;
    int blk = blockIdx.x;
    int h = blk % H;
    int tb = blk / H;
    int b = tb % B_GR;
    int t = tb / B_GR;
    int base = t * N_NODES + b * NPG;
    int tid = threadIdx.x;
    for (int i = tid; i < NPG * Q; i += blockDim.x) {
        int n = i / Q, q = i % Q;
        *(float4*)&tile[n * C + q * 4] =
            *(const float4*)(Y + (size_t)(base + n) * HC + h * C + q * 4);
    }
    for (int i = tid; i < NPG * 16; i += blockDim.x)
        lsrc[i] = src[(size_t)(b * NPG) * 16 + i] - b * NPG;
    __syncthreads();
    for (int task = tid; task < NPG * Q; task += blockDim.x) {
        int n = task / Q, q = task % Q;
        const float* ap = g_alpha + ((size_t)(base + n) * H + h) * 17;
        float4 acc = make_float4(0.f, 0.f, 0.f, 0.f);
        #pragma unroll
        for (int k = 0; k < 16; k++) {
            float a = ap[k];
            float4 v = *(const float4*)&tile[lsrc[n * 16 + k] * C + q * 4];
            acc.x = fmaf(a, v.x, acc.x); acc.y = fmaf(a, v.y, acc.y);
            acc.z = fmaf(a, v.z, acc.z); acc.w = fmaf(a, v.w, acc.w);
        }
        {
            float a = ap[16];
            float4 v = *(const float4*)&tile[n * C + q * 4];
            acc.x = fmaf(a, v.x, acc.x); acc.y = fmaf(a, v.y, acc.y);
            acc.z = fmaf(a, v.z, acc.z); acc.w = fmaf(a, v.w, acc.w);
        }
        float4 bb = *(const float4*)(bias + h * C + q * 4);
        float4 o;
        o.x = elu_f(acc.x + bb.x); o.y = elu_f(acc.y + bb.y);
        o.z = elu_f(acc.z + bb.z); o.w = elu_f(acc.w + bb.w);
        *(float4*)(Xout + (size_t)(base + n) * HC + h * C + q * 4) = o;
    }
}

// ---------------- mean pool ----------------
__global__ void pool_kernel(const float* __restrict__ X4) {
    int tb = blockIdx.x;
    int t = tb / B_GR, b = tb % B_GR;
    int tid = threadIdx.x;
    float acc[8] = {};
    for (int nn = tid; nn < NPG; nn += blockDim.x) {
        const float* p = X4 + ((size_t)(t * N_NODES + b * NPG + nn)) * 8;
        #pragma unroll
        for (int f = 0; f < 8; f++) acc[f] += p[f];
    }
    __shared__ float s[8];
    if (tid < 8) s[tid] = 0.f;
    __syncthreads();
    #pragma unroll
    for (int f = 0; f < 8; f++) atomicAdd(&s[f], acc[f]);
    __syncthreads();
    if (tid < 8) g_emb[tb * 8 + tid] = s[tid] * (1.0f / (float)NPG);
}

// ---------------- LSTM + FC ----------------
__device__ __forceinline__ float sigmoidf(float x) { return 1.f / (1.f + expf(-x)); }

__global__ void lstm_fc(const float* __restrict__ w_ih, const float* __restrict__ w_hh,
                        const float* __restrict__ b_ih, const float* __restrict__ b_hh,
                        const float* __restrict__ w_fc, const float* __restrict__ b_fc,
                        float* __restrict__ out) {
    __shared__ float h[8][128], c[8][128], g[8][512], xs[8][8];
    int tid = threadIdx.x;
    for (int i = tid; i < 8 * 128; i += 1024) { ((float*)h)[i] = 0.f; ((float*)c)[i] = 0.f; }
    __syncthreads();
    for (int t = 0; t < T_STEPS; t++) {
        if (tid < 64) xs[tid >> 3][tid & 7] = g_emb[t * 64 + tid];
        __syncthreads();
        #pragma unroll
        for (int task = tid; task < 4096; task += 1024) {
            int b = task >> 9, row = task & 511;
            float acc = b_ih[row] + b_hh[row];
            const float* wi = w_ih + row * 8;
            #pragma unroll
            for (int k = 0; k < 8; k++) acc += xs[b][k] * wi[k];
            const float* wh = w_hh + row * 128;
            #pragma unroll 8
            for (int j = 0; j < 128; j++) acc += h[b][j] * wh[j];
            g[b][row] = acc;
        }
        __syncthreads();
        if (tid < 1024) {
            int b = tid >> 7, u = tid & 127;
            float ig = sigmoidf(g[b][u]);
            float fg = sigmoidf(g[b][128 + u]);
            float gg = tanhf(g[b][256 + u]);
            float og = sigmoidf(g[b][384 + u]);
            float cn = fg * c[b][u] + ig * gg;
            c[b][u] = cn;
            h[b][u] = og * tanhf(cn);
        }
        __syncthreads();
    }
    if (tid < 16) {
        int b = tid >> 1, o = tid & 1;
        float acc = b_fc[o];
        const float* w = w_fc + o * 128;
        #pragma unroll 8
        for (int j = 0; j < 128; j++) acc += h[b][j] * w[j];
        out[b * 2 + o] = acc;
    }
}

// ---------------- host launch ----------------
extern "C" void kernel_launch(void* const* d_in, const int* in_sizes, int n_in,
                              void* d_out, int out_size) {
    const float *x_seq = 0, *W1 = 0, *as1 = 0, *ad1 = 0, *b1 = 0;
    const float *W2 = 0, *as2 = 0, *ad2 = 0, *b2 = 0;
    const float *W3 = 0, *as3 = 0, *ad3 = 0, *b3 = 0;
    const float *W4 = 0, *as4 = 0, *ad4 = 0, *b4 = 0;
    const float *w_ih = 0, *w_hh = 0, *b_ih = 0, *b_hh = 0, *w_fc = 0, *b_fc = 0;
    const int *edge = 0;
    int c1024 = 0, c512 = 0, c256 = 0, c128 = 0, c8 = 0;
    for (int i = 0; i < n_in; i++) {
        const float* p = (const float*)d_in[i];
        switch (in_sizes[i]) {
            case 172800: x_seq = p; break;
            case 276480: edge = (const int*)p; break;
            case 8640:   break;
            case 131072: W2 = p; break;
            case 65536:  w_hh = p; break;
            case 32768:  W3 = p; break;
            case 4096:   w_ih = p; break;
            case 1024:   { if (c1024++ == 0) W1 = p; else W4 = p; } break;
            case 512: { int k = c512++;
                if (k == 0) as1 = p; else if (k == 1) ad1 = p; else if (k == 2) b1 = p;
                else if (k == 3) b_ih = p; else b_hh = p; } break;
            case 256: { int k = c256++;
                if (k == 0) as2 = p; else if (k == 1) ad2 = p; else if (k == 2) b2 = p;
                else w_fc = p; } break;
            case 128: { int k = c128++;
                if (k == 0) as3 = p; else if (k == 1) ad3 = p; else b3 = p; } break;
            case 8: { int k = c8++;
                if (k == 0) as4 = p; else if (k == 1) ad4 = p; else b4 = p; } break;
            case 2: b_fc = p; break;
            default: break;
        }
    }
    const int* src = edge;

    float *bufA, *bufB;
    cudaGetSymbolAddress((void**)&bufA, g_bufA);
    cudaGetSymbolAddress((void**)&bufB, g_bufB);

    // smem sizes
    const int SM_ALPHA8 = (NPG * 8 + 135 * 16) * 4;      // 51840
    const int SM_ALPHA1 = (NPG * 1 + 135 * 16) * 4;      // 12960
    const int SM_AGG_32 = (NPG * 32 + NPG * 16) * 4;     // 207360
    const int SM_AGG_16 = (NPG * 16 + NPG * 16) * 4;     // 138240
    const int SM_AGG_8  = (NPG * 8 + NPG * 16) * 4;      // 103680
    cudaFuncSetAttribute(alpha_kernel<8>, cudaFuncAttributeMaxDynamicSharedMemorySize, SM_ALPHA8);
    cudaFuncSetAttribute(gat_agg<8, 32>, cudaFuncAttributeMaxDynamicSharedMemorySize, SM_AGG_32);
    cudaFuncSetAttribute(gat_agg<8, 16>, cudaFuncAttributeMaxDynamicSharedMemorySize, SM_AGG_16);
    cudaFuncSetAttribute(gat_agg<1, 8>,  cudaFuncAttributeMaxDynamicSharedMemorySize, SM_AGG_8);

    // ---- Layer 1 ----
    uvec_l1<<<1, 32>>>(W1, as1, ad1);
    esed_l1<<<(TN * 8 + 255) / 256, 256>>>(x_seq);
    alpha_kernel<8><<<T_STEPS * B_GR * 8, 256, SM_ALPHA8>>>(src);
    z_agg<<<T_STEPS * B_GR * 8, 256>>>(x_seq, src);
    l1_out<<<(TN * 128 + 255) / 256, 256>>>(W1, b1, bufB);

    // ---- Layer 2: [TN,512] @ [512,256] ----
    gemm128<<<dim3(2, TN / 128), 256>>>(bufB, W2, bufA, TN, 512, 256);
    attn_coef<8, 32><<<(TN * 8 + 255) / 256, 256>>>(bufA, as2, ad2);
    alpha_kernel<8><<<T_STEPS * B_GR * 8, 256, SM_ALPHA8>>>(src);
    gat_agg<8, 32><<<T_STEPS * B_GR * 8, 256, SM_AGG_32>>>(bufA, src, b2, bufB);

    // ---- Layer 3: [TN,256] @ [256,128] ----
    gemm128<<<dim3(1, TN / 128), 256>>>(bufB, W3, bufA, TN, 256, 128);
    attn_coef<8, 16><<<(TN * 8 + 255) / 256, 256>>>(bufA, as3, ad3);
    alpha_kernel<8><<<T_STEPS * B_GR * 8, 256, SM_ALPHA8>>>(src);
    gat_agg<8, 16><<<T_STEPS * B_GR * 8, 256, SM_AGG_16>>>(bufA, src, b3, bufB);

    // ---- Layer 4: [TN,128] @ [128,8] ----
    gemm_l4<<<(TN * 8 + 255) / 256, 256>>>(bufB, W4, bufA);
    attn_coef<1, 8><<<(TN + 255) / 256, 256>>>(bufA, as4, ad4);
    alpha_kernel<1><<<T_STEPS * B_GR * 8, 256, SM_ALPHA1>>>(src);
    gat_agg<1, 8><<<T_STEPS * B_GR, 256, SM_AGG_8>>>(bufA, src, b4, bufB);

    // ---- pool + LSTM + FC ----
    pool_kernel<<<T_STEPS * B_GR, 256>>>(bufB);
    lstm_fc<<<1, 1024>>>(w_ih, w_hh, b_ih, b_hh, w_fc, b_fc, (float*)d_out);
}

// round 3
// speedup vs baseline: 2.0589x; 2.0417x over previous
#include <cuda_runtime.h>
#include <math.h>

#define T_STEPS 10
#define B_GR    8
#define NPG     1080
#define N_NODES 8640
#define TN      86400
#define DEG     16

// ---------------- scratch ----------------
__device__ float g_bufA[(size_t)TN * 256];
__device__ float g_bufB[(size_t)TN * 512];
__device__ float g_es[TN * 8];
__device__ float g_ed[TN * 8];
// alpha planes: [ (t*B+b)*H + h ][ node 0..NPG ) ][ k 0..17 )
__device__ float g_alpha[(size_t)T_STEPS * B_GR * 8 * NPG * 17];
__device__ float g_z[TN * 16];
__device__ float g_emb[T_STEPS * B_GR * 8];
__device__ float g_uv[32];
__device__ int   g_lsrc[N_NODES * 16];    // graph-local src indices (0..NPG)

// ---------------- fast exp for x <= 0 (FMA pipe only) ----------------
__device__ __forceinline__ float exp_neg(float x) {
    x = fmaxf(x, -87.0f);
    const float L2E = 1.4426950408889634f;
    float z = fmaf(x, L2E, 12582912.0f);
    int   ei = __float_as_int(z);
    float n = z - 12582912.0f;
    float f = fmaf(x, L2E, -n);
    float r = fmaf(1.5403530e-4f, f, 1.3333558e-3f);
    r = fmaf(r, f, 9.6181291e-3f);
    r = fmaf(r, f, 5.5504109e-2f);
    r = fmaf(r, f, 2.4022651e-1f);
    r = fmaf(r, f, 6.9314718e-1f);
    r = fmaf(r, f, 1.0f);
    float s = __int_as_float((ei + 127) << 23);
    return r * s;
}
__device__ __forceinline__ float elu_f(float v) { return v > 0.f ? v : exp_neg(v) - 1.f; }

// ---------------- prep: graph-local src ----------------
__global__ void prep_lsrc(const int* __restrict__ src) {
    int i = blockIdx.x * blockDim.x + threadIdx.x;
    if (i >= N_NODES * 16) return;
    int b = i / (NPG * 16);
    g_lsrc[i] = src[i] - b * NPG;
}

// ---------------- layer 1: fold W1 into attention vectors ----------------
__global__ void uvec_l1(const float* __restrict__ W1, const float* __restrict__ as1,
                        const float* __restrict__ ad1) {
    int tid = threadIdx.x;
    if (tid < 32) {
        int d = tid >> 4, h = (tid >> 1) & 7, f = tid & 1;
        const float* a = d ? ad1 : as1;
        float s = 0.f;
        #pragma unroll
        for (int c = 0; c < 64; c++) s += W1[f * 512 + h * 64 + c] * a[h * 64 + c];
        g_uv[tid] = s;
    }
}

__global__ void esed_l1(const float* __restrict__ x) {
    int idx = blockIdx.x * blockDim.x + threadIdx.x;
    if (idx >= TN * 8) return;
    int row = idx >> 3, h = idx & 7;
    float x0 = x[row * 2], x1 = x[row * 2 + 1];
    g_es[idx] = x0 * g_uv[h * 2]      + x1 * g_uv[h * 2 + 1];
    g_ed[idx] = x0 * g_uv[16 + h * 2] + x1 * g_uv[16 + h * 2 + 1];
}

// ---------------- alpha precompute: writes plane layout [plane][n][17] ----------------
// grid: T*B*8 (chunks of 135 nodes)
template<int H>
__global__ void alpha_kernel() {
    extern __shared__ float sm[];
    float* es_s = sm;                       // NPG*H
    int*   lsrcS = (int*)(sm + NPG * H);    // 135*16
    int blk = blockIdx.x;
    int chunk = blk & 7;
    int tb = blk >> 3;
    int b = tb & 7;
    int t = tb >> 3;
    int base = t * N_NODES + b * NPG;
    int tid = threadIdx.x;
    for (int i = tid; i < NPG * H; i += blockDim.x)
        es_s[i] = g_es[(size_t)base * H + i];
    int n0 = chunk * 135;
    for (int i = tid; i < 135 * 16; i += blockDim.x)
        lsrcS[i] = g_lsrc[(size_t)(b * NPG + n0) * 16 + i];
    __syncthreads();
    for (int task = tid; task < 135 * H; task += blockDim.x) {
        int nl = task / H, h = task % H;
        int n = n0 + nl;
        float ed = g_ed[(size_t)(base + n) * H + h];
        float ev[17];
        float m = -1e30f;
        #pragma unroll
        for (int k = 0; k < 16; k++) {
            float e = es_s[lsrcS[nl * 16 + k] * H + h] + ed;
            e = e >= 0.f ? e : 0.2f * e;
            ev[k] = e; m = fmaxf(m, e);
        }
        {
            float e = es_s[n * H + h] + ed;
            e = e >= 0.f ? e : 0.2f * e;
            ev[16] = e; m = fmaxf(m, e);
        }
        float s = 0.f;
        #pragma unroll
        for (int k = 0; k < 17; k++) { float v = exp_neg(ev[k] - m); ev[k] = v; s += v; }
        float inv = 1.f / (s + 1e-16f);
        float* ap = g_alpha + ((size_t)(tb * H + h) * NPG + n) * 17;
        #pragma unroll
        for (int k = 0; k < 17; k++) ap[k] = ev[k] * inv;
    }
}

// ---------------- layer-1 aggregation into z[TN,16] (alpha staged in smem) ----------------
__global__ void z_agg(const float* __restrict__ x) {
    extern __shared__ float sm[];
    float* alphaS = sm;                       // 8 * 135 * 17 = 18360
    float* xs     = sm + 18360;               // NPG*2
    int*   lsrcS  = (int*)(xs + NPG * 2);     // 135*16
    int blk = blockIdx.x;
    int chunk = blk & 7;
    int tb = blk >> 3;
    int b = tb & 7;
    int t = tb >> 3;
    int base = t * N_NODES + b * NPG;
    int n0 = chunk * 135;
    int tid = threadIdx.x;
    for (int i = tid; i < NPG * 2; i += blockDim.x) xs[i] = x[(size_t)base * 2 + i];
    for (int i = tid; i < 135 * 16; i += blockDim.x)
        lsrcS[i] = g_lsrc[(size_t)(b * NPG + n0) * 16 + i];
    // stage 8 head-planes of alpha for this chunk (coalesced)
    for (int i = tid; i < 8 * 135 * 17; i += blockDim.x) {
        int h = i / (135 * 17), r = i % (135 * 17);
        alphaS[i] = g_alpha[((size_t)(tb * 8 + h) * NPG + n0) * 17 + r];
    }
    __syncthreads();
    for (int task = tid; task < 135 * 16; task += blockDim.x) {
        int nl = task >> 4, hf = task & 15;
        int h = hf >> 1, f = hf & 1;
        const float* ap = alphaS + h * (135 * 17) + nl * 17;
        float acc = 0.f;
        #pragma unroll
        for (int k = 0; k < 16; k++) acc = fmaf(ap[k], xs[lsrcS[nl * 16 + k] * 2 + f], acc);
        acc = fmaf(ap[16], xs[(n0 + nl) * 2 + f], acc);
        g_z[(size_t)(base + n0 + nl) * 16 + hf] = acc;
    }
}

// ---------------- layer-1 output expansion ----------------
__global__ void l1_out(const float* __restrict__ W1, const float* __restrict__ b1,
                       float* __restrict__ X1) {
    int idx = blockIdx.x * blockDim.x + threadIdx.x;
    if (idx >= TN * 128) return;
    int row = idx >> 7, q = idx & 127;
    int h = q >> 4;
    float z0 = g_z[(size_t)row * 16 + h * 2];
    float z1 = g_z[(size_t)row * 16 + h * 2 + 1];
    float4 w0 = *(const float4*)(W1 + q * 4);
    float4 w1 = *(const float4*)(W1 + 512 + q * 4);
    float4 bb = *(const float4*)(b1 + q * 4);
    float4 v;
    v.x = elu_f(fmaf(z0, w0.x, fmaf(z1, w1.x, bb.x)));
    v.y = elu_f(fmaf(z0, w0.y, fmaf(z1, w1.y, bb.y)));
    v.z = elu_f(fmaf(z0, w0.z, fmaf(z1, w1.z, bb.z)));
    v.w = elu_f(fmaf(z0, w0.w, fmaf(z1, w1.w, bb.w)));
    *(float4*)(X1 + (size_t)row * 512 + q * 4) = v;
}

// ---------------- 128x128 fp32 GEMM ----------------
__global__ __launch_bounds__(256, 2)
void gemm128(const float* __restrict__ A, const float* __restrict__ W,
             float* __restrict__ C, int M, int K, int Nc) {
    __shared__ float As[16][136];
    __shared__ float Ws[16][136];
    const int tid = threadIdx.x;
    const int tx = tid & 15, ty = tid >> 4;
    const int rb = blockIdx.y * 128, cb = blockIdx.x * 128;
    const int arow = tid >> 1, ap = tid & 1;
    const int wk = tid >> 5, wc = tid & 31;
    float acc[8][8] = {};
    for (int k0 = 0; k0 < K; k0 += 16) {
        const float* abase = A + (size_t)(rb + arow) * K + k0 + ap * 8;
        float4 av0 = *(const float4*)(abase);
        float4 av1 = *(const float4*)(abase + 4);
        float4 wv0 = *(const float4*)(W + (size_t)(k0 + wk) * Nc + cb + wc * 4);
        float4 wv1 = *(const float4*)(W + (size_t)(k0 + wk + 8) * Nc + cb + wc * 4);
        __syncthreads();
        As[ap * 8 + 0][arow] = av0.x; As[ap * 8 + 1][arow] = av0.y;
        As[ap * 8 + 2][arow] = av0.z; As[ap * 8 + 3][arow] = av0.w;
        As[ap * 8 + 4][arow] = av1.x; As[ap * 8 + 5][arow] = av1.y;
        As[ap * 8 + 6][arow] = av1.z; As[ap * 8 + 7][arow] = av1.w;
        *(float4*)&Ws[wk][wc * 4] = wv0;
        *(float4*)&Ws[wk + 8][wc * 4] = wv1;
        __syncthreads();
        #pragma unroll
        for (int k = 0; k < 16; k++) {
            float4 a0 = *(const float4*)&As[k][ty * 4];
            float4 a1 = *(const float4*)&As[k][64 + ty * 4];
            float4 b0 = *(const float4*)&Ws[k][tx * 4];
            float4 b1 = *(const float4*)&Ws[k][64 + tx * 4];
            float a[8] = {a0.x, a0.y, a0.z, a0.w, a1.x, a1.y, a1.z, a1.w};
            float bv[8] = {b0.x, b0.y, b0.z, b0.w, b1.x, b1.y, b1.z, b1.w};
            #pragma unroll
            for (int i = 0; i < 8; i++)
                #pragma unroll
                for (int j = 0; j < 8; j++)
                    acc[i][j] = fmaf(a[i], bv[j], acc[i][j]);
        }
    }
    #pragma unroll
    for (int i = 0; i < 8; i++) {
        int r = rb + ((i < 4) ? (ty * 4 + i) : (64 + ty * 4 + i - 4));
        float4 v0 = make_float4(acc[i][0], acc[i][1], acc[i][2], acc[i][3]);
        float4 v1 = make_float4(acc[i][4], acc[i][5], acc[i][6], acc[i][7]);
        *(float4*)(C + (size_t)r * Nc + cb + tx * 4) = v0;
        *(float4*)(C + (size_t)r * Nc + cb + 64 + tx * 4) = v1;
    }
}

// ---------------- L4 GEMM: [TN,128] @ [128,8] ----------------
__global__ void gemm_l4(const float* __restrict__ X, const float* __restrict__ W4,
                        float* __restrict__ Y) {
    __shared__ float w[128 * 8];
    int tid = threadIdx.x;
    for (int i = tid; i < 1024; i += blockDim.x) w[i] = W4[i];
    __syncthreads();
    int idx = blockIdx.x * blockDim.x + tid;
    if (idx >= TN * 8) return;
    int row = idx >> 3, j = idx & 7;
    const float4* xr = (const float4*)(X + (size_t)row * 128);
    float acc = 0.f;
    #pragma unroll 8
    for (int k = 0; k < 32; k++) {
        float4 v = xr[k];
        acc = fmaf(v.x, w[(k * 4 + 0) * 8 + j], acc);
        acc = fmaf(v.y, w[(k * 4 + 1) * 8 + j], acc);
        acc = fmaf(v.z, w[(k * 4 + 2) * 8 + j], acc);
        acc = fmaf(v.w, w[(k * 4 + 3) * 8 + j], acc);
    }
    Y[idx] = acc;
}

// ---------------- attention coefficients ----------------
template<int H, int C>
__global__ void attn_coef(const float* __restrict__ Y, const float* __restrict__ as_,
                          const float* __restrict__ ad_) {
    int idx = blockIdx.x * blockDim.x + threadIdx.x;
    if (idx >= TN * H) return;
    int row = idx / H, h = idx % H;
    const float* y = Y + (size_t)row * (H * C) + h * C;
    float se = 0.f, de = 0.f;
    #pragma unroll
    for (int c = 0; c < C; c += 4) {
        float4 v = *(const float4*)(y + c);
        float4 a = *(const float4*)(as_ + h * C + c);
        float4 d = *(const float4*)(ad_ + h * C + c);
        se += v.x * a.x + v.y * a.y + v.z * a.z + v.w * a.w;
        de += v.x * d.x + v.y * d.y + v.z * d.z + v.w * d.w;
    }
    g_es[idx] = se;
    g_ed[idx] = de;
}

// ---------------- graph-tiled GAT aggregation, alpha staged in smem ----------------
// grid: T*B*H ; block 512 ; smem: tile[NPG*C] + alphaS[NPG*17] (+ lsrcS[NPG*16] if it fits)
template<int H, int C, bool LSRC_SMEM>
__global__ __launch_bounds__(512, 1)
void gat_agg(const float* __restrict__ Y, const float* __restrict__ bias,
             float* __restrict__ Xout) {
    extern __shared__ float sm[];
    float* tile   = sm;                         // NPG*C
    float* alphaS = sm + NPG * C;               // NPG*17
    int*   lsrcS  = (int*)(alphaS + NPG * 17);  // NPG*16 (optional)
    constexpr int HC = H * C;
    constexpr int Q = C / 4;
    int blk = blockIdx.x;
    int h = blk % H;
    int tb = blk / H;
    int b = tb % B_GR;
    int t = tb / B_GR;
    int base = t * N_NODES + b * NPG;
    int tid = threadIdx.x;
    for (int i = tid; i < NPG * Q; i += blockDim.x) {
        int n = i / Q, q = i % Q;
        *(float4*)&tile[n * C + q * 4] =
            *(const float4*)(Y + (size_t)(base + n) * HC + h * C + q * 4);
    }
    {
        const float* ag = g_alpha + (size_t)(tb * H + h) * NPG * 17;
        for (int i = tid; i < NPG * 17; i += blockDim.x) alphaS[i] = ag[i];
    }
    if (LSRC_SMEM) {
        const int* lg = g_lsrc + (size_t)b * NPG * 16;
        for (int i = tid; i < NPG * 16; i += blockDim.x) lsrcS[i] = lg[i];
    }
    __syncthreads();
    const int* lg = g_lsrc + (size_t)b * NPG * 16;
    for (int task = tid; task < NPG * Q; task += blockDim.x) {
        int n = task / Q, q = task % Q;
        const float* ap = alphaS + n * 17;
        float4 acc = make_float4(0.f, 0.f, 0.f, 0.f);
        #pragma unroll
        for (int k = 0; k < 16; k++) {
            int idx = LSRC_SMEM ? lsrcS[n * 16 + k] : lg[n * 16 + k];
            float a = ap[k];
            float4 v = *(const float4*)&tile[idx * C + q * 4];
            acc.x = fmaf(a, v.x, acc.x); acc.y = fmaf(a, v.y, acc.y);
            acc.z = fmaf(a, v.z, acc.z); acc.w = fmaf(a, v.w, acc.w);
        }
        {
            float a = ap[16];
            float4 v = *(const float4*)&tile[n * C + q * 4];
            acc.x = fmaf(a, v.x, acc.x); acc.y = fmaf(a, v.y, acc.y);
            acc.z = fmaf(a, v.z, acc.z); acc.w = fmaf(a, v.w, acc.w);
        }
        float4 bb = *(const float4*)(bias + h * C + q * 4);
        float4 o;
        o.x = elu_f(acc.x + bb.x); o.y = elu_f(acc.y + bb.y);
        o.z = elu_f(acc.z + bb.z); o.w = elu_f(acc.w + bb.w);
        *(float4*)(Xout + (size_t)(base + n) * HC + h * C + q * 4) = o;
    }
}

// ---------------- mean pool ----------------
__global__ void pool_kernel(const float* __restrict__ X4) {
    int tb = blockIdx.x;
    int t = tb / B_GR, b = tb % B_GR;
    int tid = threadIdx.x;
    float acc[8] = {};
    for (int nn = tid; nn < NPG; nn += blockDim.x) {
        const float* p = X4 + ((size_t)(t * N_NODES + b * NPG + nn)) * 8;
        #pragma unroll
        for (int f = 0; f < 8; f++) acc[f] += p[f];
    }
    __shared__ float s[8];
    if (tid < 8) s[tid] = 0.f;
    __syncthreads();
    #pragma unroll
    for (int f = 0; f < 8; f++) atomicAdd(&s[f], acc[f]);
    __syncthreads();
    if (tid < 8) g_emb[tb * 8 + tid] = s[tid] * (1.0f / (float)NPG);
}

// ---------------- LSTM + FC ----------------
__device__ __forceinline__ float sigmoidf(float x) { return 1.f / (1.f + expf(-x)); }

__global__ void lstm_fc(const float* __restrict__ w_ih, const float* __restrict__ w_hh,
                        const float* __restrict__ b_ih, const float* __restrict__ b_hh,
                        const float* __restrict__ w_fc, const float* __restrict__ b_fc,
                        float* __restrict__ out) {
    __shared__ float h[8][128], c[8][128], g[8][512], xs[8][8];
    int tid = threadIdx.x;
    for (int i = tid; i < 8 * 128; i += 1024) { ((float*)h)[i] = 0.f; ((float*)c)[i] = 0.f; }
    __syncthreads();
    for (int t = 0; t < T_STEPS; t++) {
        if (tid < 64) xs[tid >> 3][tid & 7] = g_emb[t * 64 + tid];
        __syncthreads();
        #pragma unroll
        for (int task = tid; task < 4096; task += 1024) {
            int b = task >> 9, row = task & 511;
            float acc = b_ih[row] + b_hh[row];
            const float* wi = w_ih + row * 8;
            #pragma unroll
            for (int k = 0; k < 8; k++) acc += xs[b][k] * wi[k];
            const float4* wh = (const float4*)(w_hh + row * 128);
            const float4* hb = (const float4*)h[b];
            #pragma unroll 8
            for (int j = 0; j < 32; j++) {
                float4 w4 = wh[j], h4 = hb[j];
                acc = fmaf(w4.x, h4.x, acc); acc = fmaf(w4.y, h4.y, acc);
                acc = fmaf(w4.z, h4.z, acc); acc = fmaf(w4.w, h4.w, acc);
            }
            g[b][row] = acc;
        }
        __syncthreads();
        if (tid < 1024) {
            int b = tid >> 7, u = tid & 127;
            float ig = sigmoidf(g[b][u]);
            float fg = sigmoidf(g[b][128 + u]);
            float gg = tanhf(g[b][256 + u]);
            float og = sigmoidf(g[b][384 + u]);
            float cn = fg * c[b][u] + ig * gg;
            c[b][u] = cn;
            h[b][u] = og * tanhf(cn);
        }
        __syncthreads();
    }
    if (tid < 16) {
        int b = tid >> 1, o = tid & 1;
        float acc = b_fc[o];
        const float* w = w_fc + o * 128;
        #pragma unroll 8
        for (int j = 0; j < 128; j++) acc += h[b][j] * w[j];
        out[b * 2 + o] = acc;
    }
}

// ---------------- host launch ----------------
extern "C" void kernel_launch(void* const* d_in, const int* in_sizes, int n_in,
                              void* d_out, int out_size) {
    const float *x_seq = 0, *W1 = 0, *as1 = 0, *ad1 = 0, *b1 = 0;
    const float *W2 = 0, *as2 = 0, *ad2 = 0, *b2 = 0;
    const float *W3 = 0, *as3 = 0, *ad3 = 0, *b3 = 0;
    const float *W4 = 0, *as4 = 0, *ad4 = 0, *b4 = 0;
    const float *w_ih = 0, *w_hh = 0, *b_ih = 0, *b_hh = 0, *w_fc = 0, *b_fc = 0;
    const int *edge = 0;
    int c1024 = 0, c512 = 0, c256 = 0, c128 = 0, c8 = 0;
    for (int i = 0; i < n_in; i++) {
        const float* p = (const float*)d_in[i];
        switch (in_sizes[i]) {
            case 172800: x_seq = p; break;
            case 276480: edge = (const int*)p; break;
            case 8640:   break;
            case 131072: W2 = p; break;
            case 65536:  w_hh = p; break;
            case 32768:  W3 = p; break;
            case 4096:   w_ih = p; break;
            case 1024:   { if (c1024++ == 0) W1 = p; else W4 = p; } break;
            case 512: { int k = c512++;
                if (k == 0) as1 = p; else if (k == 1) ad1 = p; else if (k == 2) b1 = p;
                else if (k == 3) b_ih = p; else b_hh = p; } break;
            case 256: { int k = c256++;
                if (k == 0) as2 = p; else if (k == 1) ad2 = p; else if (k == 2) b2 = p;
                else w_fc = p; } break;
            case 128: { int k = c128++;
                if (k == 0) as3 = p; else if (k == 1) ad3 = p; else b3 = p; } break;
            case 8: { int k = c8++;
                if (k == 0) as4 = p; else if (k == 1) ad4 = p; else b4 = p; } break;
            case 2: b_fc = p; break;
            default: break;
        }
    }
    const int* src = edge;

    float *bufA, *bufB;
    cudaGetSymbolAddress((void**)&bufA, g_bufA);
    cudaGetSymbolAddress((void**)&bufB, g_bufB);

    const int SM_ALPHA8 = (NPG * 8 + 135 * 16) * 4;                    // 43200
    const int SM_ALPHA1 = (NPG * 1 + 135 * 16) * 4;                    // 12960
    const int SM_ZAGG   = (8 * 135 * 17 + NPG * 2 + 135 * 16) * 4;     // 90720
    const int SM_AGG_32 = (NPG * 32 + NPG * 17) * 4;                   // 211680
    const int SM_AGG_16 = (NPG * 16 + NPG * 17 + NPG * 16) * 4;        // 211680
    const int SM_AGG_8  = (NPG * 8  + NPG * 17 + NPG * 16) * 4;        // 177120
    cudaFuncSetAttribute(alpha_kernel<8>, cudaFuncAttributeMaxDynamicSharedMemorySize, SM_ALPHA8);
    cudaFuncSetAttribute(alpha_kernel<1>, cudaFuncAttributeMaxDynamicSharedMemorySize, SM_ALPHA1);
    cudaFuncSetAttribute(z_agg, cudaFuncAttributeMaxDynamicSharedMemorySize, SM_ZAGG);
    cudaFuncSetAttribute(gat_agg<8, 32, false>, cudaFuncAttributeMaxDynamicSharedMemorySize, SM_AGG_32);
    cudaFuncSetAttribute(gat_agg<8, 16, true>,  cudaFuncAttributeMaxDynamicSharedMemorySize, SM_AGG_16);
    cudaFuncSetAttribute(gat_agg<1, 8, true>,   cudaFuncAttributeMaxDynamicSharedMemorySize, SM_AGG_8);

    prep_lsrc<<<(N_NODES * 16 + 255) / 256, 256>>>(src);

    // ---- Layer 1 ----
    uvec_l1<<<1, 32>>>(W1, as1, ad1);
    esed_l1<<<(TN * 8 + 255) / 256, 256>>>(x_seq);
    alpha_kernel<8><<<T_STEPS * B_GR * 8, 256, SM_ALPHA8>>>();
    z_agg<<<T_STEPS * B_GR * 8, 256, SM_ZAGG>>>(x_seq);
    l1_out<<<(TN * 128 + 255) / 256, 256>>>(W1, b1, bufB);

    // ---- Layer 2: [TN,512] @ [512,256] ----
    gemm128<<<dim3(2, TN / 128), 256>>>(bufB, W2, bufA, TN, 512, 256);
    attn_coef<8, 32><<<(TN * 8 + 255) / 256, 256>>>(bufA, as2, ad2);
    alpha_kernel<8><<<T_STEPS * B_GR * 8, 256, SM_ALPHA8>>>();
    gat_agg<8, 32, false><<<T_STEPS * B_GR * 8, 512, SM_AGG_32>>>(bufA, b2, bufB);

    // ---- Layer 3: [TN,256] @ [256,128] ----
    gemm128<<<dim3(1, TN / 128), 256>>>(bufB, W3, bufA, TN, 256, 128);
    attn_coef<8, 16><<<(TN * 8 + 255) / 256, 256>>>(bufA, as3, ad3);
    alpha_kernel<8><<<T_STEPS * B_GR * 8, 256, SM_ALPHA8>>>();
    gat_agg<8, 16, true><<<T_STEPS * B_GR * 8, 512, SM_AGG_16>>>(bufA, b3, bufB);

    // ---- Layer 4: [TN,128] @ [128,8] ----
    gemm_l4<<<(TN * 8 + 255) / 256, 256>>>(bufB, W4, bufA);
    attn_coef<1, 8><<<(TN + 255) / 256, 256>>>(bufA, as4, ad4);
    alpha_kernel<1><<<T_STEPS * B_GR * 8, 256, SM_ALPHA1>>>();
    gat_agg<1, 8, true><<<T_STEPS * B_GR, 512, SM_AGG_8>>>(bufA, b4, bufB);

    // ---- pool + LSTM + FC ----
    pool_kernel<<<T_STEPS * B_GR, 256>>>(bufB);
    lstm_fc<<<1, 1024>>>(w_ih, w_hh, b_ih, b_hh, w_fc, b_fc, (float*)d_out);
}

// round 4
// speedup vs baseline: 2.3119x; 1.1229x over previous
#include <cuda_runtime.h>
#include <math.h>

#define T_STEPS 10
#define B_GR    8
#define NPG     1080
#define N_NODES 8640
#define TN      86400
#define DEG     16

// ---------------- scratch ----------------
__device__ float g_bufA[(size_t)TN * 256];
__device__ float g_bufB[(size_t)TN * 256];
__device__ float g_z[TN * 16];
__device__ float g_emb[T_STEPS * B_GR * 8];
__device__ float g_uv[32];
__device__ int   g_lsrc[N_NODES * 16];

// ---------------- fast exp for x <= 0 (FMA pipe only) ----------------
__device__ __forceinline__ float exp_neg(float x) {
    x = fmaxf(x, -87.0f);
    const float L2E = 1.4426950408889634f;
    float z = fmaf(x, L2E, 12582912.0f);
    int   ei = __float_as_int(z);
    float n = z - 12582912.0f;
    float f = fmaf(x, L2E, -n);
    float r = fmaf(1.5403530e-4f, f, 1.3333558e-3f);
    r = fmaf(r, f, 9.6181291e-3f);
    r = fmaf(r, f, 5.5504109e-2f);
    r = fmaf(r, f, 2.4022651e-1f);
    r = fmaf(r, f, 6.9314718e-1f);
    r = fmaf(r, f, 1.0f);
    float s = __int_as_float((ei + 127) << 23);
    return r * s;
}
__device__ __forceinline__ float elu_f(float v) { return v > 0.f ? v : exp_neg(v) - 1.f; }
__device__ __forceinline__ float lrelu(float e) { return e >= 0.f ? e : 0.2f * e; }

// ---------------- prep ----------------
__global__ void prep_lsrc(const int* __restrict__ src) {
    int i = blockIdx.x * blockDim.x + threadIdx.x;
    if (i >= N_NODES * 16) return;
    int b = i / (NPG * 16);
    g_lsrc[i] = src[i] - b * NPG;
}

__global__ void uvec_l1(const float* __restrict__ W1, const float* __restrict__ as1,
                        const float* __restrict__ ad1) {
    int tid = threadIdx.x;
    if (tid < 32) {
        int d = tid >> 4, h = (tid >> 1) & 7, f = tid & 1;
        const float* a = d ? ad1 : as1;
        float s = 0.f;
        #pragma unroll
        for (int c = 0; c < 64; c++) s += W1[f * 512 + h * 64 + c] * a[h * 64 + c];
        g_uv[tid] = s;
    }
}

// ---------------- layer 1 fully fused: x -> z[TN,16] ----------------
// one block per (t,b); smem: xs[NPG*2] + es[NPG*8] + ed[NPG*8] + uv[32]
__global__ __launch_bounds__(512, 1)
void l1_fused(const float* __restrict__ x) {
    extern __shared__ float sm[];
    float* xs   = sm;                 // NPG*2
    float* es_s = xs + NPG * 2;       // NPG*8  [n*8+h]
    float* ed_s = es_s + NPG * 8;     // NPG*8
    __shared__ float uvS[32];
    int tb = blockIdx.x;
    int b = tb & 7, t = tb >> 3;
    int base = t * N_NODES + b * NPG;
    int tid = threadIdx.x;
    if (tid < 32) uvS[tid] = g_uv[tid];
    for (int i = tid; i < NPG * 2; i += blockDim.x) xs[i] = x[(size_t)base * 2 + i];
    __syncthreads();
    for (int task = tid; task < NPG * 8; task += blockDim.x) {
        int n = task >> 3, h = task & 7;
        float x0 = xs[n * 2], x1 = xs[n * 2 + 1];
        es_s[task] = fmaf(x0, uvS[h * 2], x1 * uvS[h * 2 + 1]);
        ed_s[task] = fmaf(x0, uvS[16 + h * 2], x1 * uvS[16 + h * 2 + 1]);
    }
    __syncthreads();
    for (int task = tid; task < NPG * 8; task += blockDim.x) {
        int n = task >> 3, h = task & 7;
        const int* ls = g_lsrc + ((size_t)b * NPG + n) * 16;
        float ed = ed_s[task];
        int idxs[16];
        float ev[17];
        float m = -1e30f;
        #pragma unroll
        for (int k = 0; k < 16; k++) {
            int s = ls[k];
            idxs[k] = s;
            float e = lrelu(es_s[s * 8 + h] + ed);
            ev[k] = e; m = fmaxf(m, e);
        }
        { float e = lrelu(es_s[task] + ed); ev[16] = e; m = fmaxf(m, e); }
        float ssum = 0.f;
        #pragma unroll
        for (int k = 0; k < 17; k++) { float v = exp_neg(ev[k] - m); ev[k] = v; ssum += v; }
        float inv = 1.f / (ssum + 1e-16f);
        float z0 = 0.f, z1 = 0.f;
        #pragma unroll
        for (int k = 0; k < 16; k++) {
            float a = ev[k] * inv;
            z0 = fmaf(a, xs[idxs[k] * 2], z0);
            z1 = fmaf(a, xs[idxs[k] * 2 + 1], z1);
        }
        {
            float a = ev[16] * inv;
            z0 = fmaf(a, xs[n * 2], z0);
            z1 = fmaf(a, xs[n * 2 + 1], z1);
        }
        *(float2*)&g_z[(size_t)(base + n) * 16 + h * 2] = make_float2(z0, z1);
    }
}

// ---------------- L2 GEMM with fused layer-1 expansion ----------------
// C[TN,256] = elu(z @ blockdiag(W1) + b1) @ W2 ; A generated on the fly
__global__ __launch_bounds__(256, 2)
void l1gemm(const float* __restrict__ W1, const float* __restrict__ b1,
            const float* __restrict__ W, float* __restrict__ C, int Nc) {
    __shared__ float As[16][136];
    __shared__ float Ws[16][136];
    __shared__ float zs[128][16];
    __shared__ float W1s[1024];
    __shared__ float b1s[512];
    const int tid = threadIdx.x;
    const int tx = tid & 15, ty = tid >> 4;
    const int rb = blockIdx.y * 128, cb = blockIdx.x * 128;
    const int arow = tid >> 1, ap = tid & 1;
    const int wk = tid >> 5, wc = tid & 31;
    for (int i = tid; i < 1024; i += 256) W1s[i] = W1[i];
    for (int i = tid; i < 512; i += 256) b1s[i] = b1[i];
    for (int i = tid; i < 512; i += 256)
        *(float4*)&zs[i >> 2][(i & 3) * 4] = *(const float4*)(g_z + (size_t)(rb + (i >> 2)) * 16 + (i & 3) * 4);
    __syncthreads();
    float acc[8][8] = {};
    for (int k0 = 0; k0 < 512; k0 += 16) {
        int kk = k0 + ap * 8;
        int h = kk >> 6;
        float z0 = zs[arow][h * 2], z1 = zs[arow][h * 2 + 1];
        float av[8];
        #pragma unroll
        for (int j = 0; j < 8; j++) {
            int k = kk + j;
            av[j] = elu_f(fmaf(z0, W1s[k], fmaf(z1, W1s[512 + k], b1s[k])));
        }
        float4 wv0 = *(const float4*)(W + (size_t)(k0 + wk) * Nc + cb + wc * 4);
        float4 wv1 = *(const float4*)(W + (size_t)(k0 + wk + 8) * Nc + cb + wc * 4);
        __syncthreads();
        #pragma unroll
        for (int j = 0; j < 8; j++) As[ap * 8 + j][arow] = av[j];
        *(float4*)&Ws[wk][wc * 4] = wv0;
        *(float4*)&Ws[wk + 8][wc * 4] = wv1;
        __syncthreads();
        #pragma unroll
        for (int k = 0; k < 16; k++) {
            float4 a0 = *(const float4*)&As[k][ty * 4];
            float4 a1 = *(const float4*)&As[k][64 + ty * 4];
            float4 b0 = *(const float4*)&Ws[k][tx * 4];
            float4 b1v = *(const float4*)&Ws[k][64 + tx * 4];
            float a[8] = {a0.x, a0.y, a0.z, a0.w, a1.x, a1.y, a1.z, a1.w};
            float bv[8] = {b0.x, b0.y, b0.z, b0.w, b1v.x, b1v.y, b1v.z, b1v.w};
            #pragma unroll
            for (int i = 0; i < 8; i++)
                #pragma unroll
                for (int j = 0; j < 8; j++)
                    acc[i][j] = fmaf(a[i], bv[j], acc[i][j]);
        }
    }
    #pragma unroll
    for (int i = 0; i < 8; i++) {
        int r = rb + ((i < 4) ? (ty * 4 + i) : (64 + ty * 4 + i - 4));
        *(float4*)(C + (size_t)r * Nc + cb + tx * 4) = make_float4(acc[i][0], acc[i][1], acc[i][2], acc[i][3]);
        *(float4*)(C + (size_t)r * Nc + cb + 64 + tx * 4) = make_float4(acc[i][4], acc[i][5], acc[i][6], acc[i][7]);
    }
}

// ---------------- plain 128x128 fp32 GEMM (layer 3) ----------------
__global__ __launch_bounds__(256, 2)
void gemm128(const float* __restrict__ A, const float* __restrict__ W,
             float* __restrict__ C, int K, int Nc) {
    __shared__ float As[16][136];
    __shared__ float Ws[16][136];
    const int tid = threadIdx.x;
    const int tx = tid & 15, ty = tid >> 4;
    const int rb = blockIdx.y * 128, cb = blockIdx.x * 128;
    const int arow = tid >> 1, ap = tid & 1;
    const int wk = tid >> 5, wc = tid & 31;
    float acc[8][8] = {};
    for (int k0 = 0; k0 < K; k0 += 16) {
        const float* abase = A + (size_t)(rb + arow) * K + k0 + ap * 8;
        float4 av0 = *(const float4*)(abase);
        float4 av1 = *(const float4*)(abase + 4);
        float4 wv0 = *(const float4*)(W + (size_t)(k0 + wk) * Nc + cb + wc * 4);
        float4 wv1 = *(const float4*)(W + (size_t)(k0 + wk + 8) * Nc + cb + wc * 4);
        __syncthreads();
        As[ap * 8 + 0][arow] = av0.x; As[ap * 8 + 1][arow] = av0.y;
        As[ap * 8 + 2][arow] = av0.z; As[ap * 8 + 3][arow] = av0.w;
        As[ap * 8 + 4][arow] = av1.x; As[ap * 8 + 5][arow] = av1.y;
        As[ap * 8 + 6][arow] = av1.z; As[ap * 8 + 7][arow] = av1.w;
        *(float4*)&Ws[wk][wc * 4] = wv0;
        *(float4*)&Ws[wk + 8][wc * 4] = wv1;
        __syncthreads();
        #pragma unroll
        for (int k = 0; k < 16; k++) {
            float4 a0 = *(const float4*)&As[k][ty * 4];
            float4 a1 = *(const float4*)&As[k][64 + ty * 4];
            float4 b0 = *(const float4*)&Ws[k][tx * 4];
            float4 b1 = *(const float4*)&Ws[k][64 + tx * 4];
            float a[8] = {a0.x, a0.y, a0.z, a0.w, a1.x, a1.y, a1.z, a1.w};
            float bv[8] = {b0.x, b0.y, b0.z, b0.w, b1.x, b1.y, b1.z, b1.w};
            #pragma unroll
            for (int i = 0; i < 8; i++)
                #pragma unroll
                for (int j = 0; j < 8; j++)
                    acc[i][j] = fmaf(a[i], bv[j], acc[i][j]);
        }
    }
    #pragma unroll
    for (int i = 0; i < 8; i++) {
        int r = rb + ((i < 4) ? (ty * 4 + i) : (64 + ty * 4 + i - 4));
        *(float4*)(C + (size_t)r * Nc + cb + tx * 4) = make_float4(acc[i][0], acc[i][1], acc[i][2], acc[i][3]);
        *(float4*)(C + (size_t)r * Nc + cb + 64 + tx * 4) = make_float4(acc[i][4], acc[i][5], acc[i][6], acc[i][7]);
    }
}

// ---------------- L4 GEMM ----------------
__global__ void gemm_l4(const float* __restrict__ X, const float* __restrict__ W4,
                        float* __restrict__ Y) {
    __shared__ float w[1024];
    int tid = threadIdx.x;
    for (int i = tid; i < 1024; i += blockDim.x) w[i] = W4[i];
    __syncthreads();
    int idx = blockIdx.x * blockDim.x + tid;
    if (idx >= TN * 8) return;
    int row = idx >> 3, j = idx & 7;
    const float4* xr = (const float4*)(X + (size_t)row * 128);
    float acc = 0.f;
    #pragma unroll 8
    for (int k = 0; k < 32; k++) {
        float4 v = xr[k];
        acc = fmaf(v.x, w[(k * 4 + 0) * 8 + j], acc);
        acc = fmaf(v.y, w[(k * 4 + 1) * 8 + j], acc);
        acc = fmaf(v.z, w[(k * 4 + 2) * 8 + j], acc);
        acc = fmaf(v.w, w[(k * 4 + 3) * 8 + j], acc);
    }
    Y[idx] = acc;
}

// ---------------- fully fused GAT: es/ed + softmax + aggregate ----------------
// one block per (t,b,h). smem: tile[NPG*C] + es[NPG] + ed[NPG] + alpha[NPG*17]
template<int H, int C>
__global__ __launch_bounds__(512, 1)
void fused_gat(const float* __restrict__ Y, const float* __restrict__ as_,
               const float* __restrict__ ad_, const float* __restrict__ bias,
               float* __restrict__ Xout) {
    extern __shared__ float sm[];
    constexpr int HC = H * C;
    constexpr int Q = C / 4;
    float* tile   = sm;                  // NPG*C
    float* es_s   = tile + NPG * C;      // NPG
    float* ed_s   = es_s + NPG;          // NPG
    float* alphaS = ed_s + NPG;          // NPG*17
    __shared__ float as_s[C], ad_s[C], bi_s[C];
    int blk = blockIdx.x;
    int h = (H == 1) ? 0 : (blk % H);
    int tb = (H == 1) ? blk : (blk / H);
    int b = tb % B_GR;
    int t = tb / B_GR;
    int base = t * N_NODES + b * NPG;
    int tid = threadIdx.x;
    if (tid < C) { as_s[tid] = as_[h * C + tid]; ad_s[tid] = ad_[h * C + tid]; bi_s[tid] = bias[h * C + tid]; }
    for (int i = tid; i < NPG * Q; i += blockDim.x) {
        int n = i / Q, q = i % Q;
        *(float4*)&tile[n * C + q * 4] =
            *(const float4*)(Y + (size_t)(base + n) * HC + h * C + q * 4);
    }
    __syncthreads();
    // phase 1: es/ed per node (lane-rotated to break stride-C conflicts)
    for (int n = tid; n < NPG; n += blockDim.x) {
        const float* tn = tile + n * C;
        int rot = tid & (Q - 1);
        float se = 0.f, de = 0.f;
        #pragma unroll
        for (int jj = 0; jj < Q; jj++) {
            int q = (jj + rot) & (Q - 1);
            float4 v = *(const float4*)&tn[q * 4];
            float4 a = *(const float4*)&as_s[q * 4];
            float4 d = *(const float4*)&ad_s[q * 4];
            se = fmaf(v.x, a.x, fmaf(v.y, a.y, fmaf(v.z, a.z, fmaf(v.w, a.w, se))));
            de = fmaf(v.x, d.x, fmaf(v.y, d.y, fmaf(v.z, d.z, fmaf(v.w, d.w, de))));
        }
        es_s[n] = se; ed_s[n] = de;
    }
    __syncthreads();
    // phase 2: softmax per node
    for (int n = tid; n < NPG; n += blockDim.x) {
        const int* ls = g_lsrc + ((size_t)b * NPG + n) * 16;
        float ed = ed_s[n];
        float ev[17];
        float m = -1e30f;
        #pragma unroll
        for (int k = 0; k < 16; k++) {
            float e = lrelu(es_s[ls[k]] + ed);
            ev[k] = e; m = fmaxf(m, e);
        }
        { float e = lrelu(es_s[n] + ed); ev[16] = e; m = fmaxf(m, e); }
        float ssum = 0.f;
        #pragma unroll
        for (int k = 0; k < 17; k++) { float v = exp_neg(ev[k] - m); ev[k] = v; ssum += v; }
        float inv = 1.f / (ssum + 1e-16f);
        float* ap = alphaS + n * 17;
        #pragma unroll
        for (int k = 0; k < 17; k++) ap[k] = ev[k] * inv;
    }
    __syncthreads();
    // phase 3: aggregate + bias + ELU
    const int* lg = g_lsrc + (size_t)b * NPG * 16;
    for (int task = tid; task < NPG * Q; task += blockDim.x) {
        int n = task / Q, q = task % Q;
        const float* ap = alphaS + n * 17;
        float4 acc = make_float4(0.f, 0.f, 0.f, 0.f);
        #pragma unroll
        for (int k = 0; k < 16; k++) {
            int idx = lg[n * 16 + k];
            float a = ap[k];
            float4 v = *(const float4*)&tile[idx * C + q * 4];
            acc.x = fmaf(a, v.x, acc.x); acc.y = fmaf(a, v.y, acc.y);
            acc.z = fmaf(a, v.z, acc.z); acc.w = fmaf(a, v.w, acc.w);
        }
        {
            float a = ap[16];
            float4 v = *(const float4*)&tile[n * C + q * 4];
            acc.x = fmaf(a, v.x, acc.x); acc.y = fmaf(a, v.y, acc.y);
            acc.z = fmaf(a, v.z, acc.z); acc.w = fmaf(a, v.w, acc.w);
        }
        float4 o;
        o.x = elu_f(acc.x + bi_s[q * 4 + 0]); o.y = elu_f(acc.y + bi_s[q * 4 + 1]);
        o.z = elu_f(acc.z + bi_s[q * 4 + 2]); o.w = elu_f(acc.w + bi_s[q * 4 + 3]);
        *(float4*)(Xout + (size_t)(base + n) * HC + h * C + q * 4) = o;
    }
}

// ---------------- mean pool ----------------
__global__ void pool_kernel(const float* __restrict__ X4) {
    int tb = blockIdx.x;
    int t = tb / B_GR, b = tb % B_GR;
    int tid = threadIdx.x;
    float acc[8] = {};
    for (int nn = tid; nn < NPG; nn += blockDim.x) {
        const float* p = X4 + ((size_t)(t * N_NODES + b * NPG + nn)) * 8;
        #pragma unroll
        for (int f = 0; f < 8; f++) acc[f] += p[f];
    }
    __shared__ float s[8];
    if (tid < 8) s[tid] = 0.f;
    __syncthreads();
    #pragma unroll
    for (int f = 0; f < 8; f++) atomicAdd(&s[f], acc[f]);
    __syncthreads();
    if (tid < 8) g_emb[tb * 8 + tid] = s[tid] * (1.0f / (float)NPG);
}

// ---------------- LSTM + FC ----------------
__device__ __forceinline__ float sigmoidf(float x) { return 1.f / (1.f + expf(-x)); }

__global__ void lstm_fc(const float* __restrict__ w_ih, const float* __restrict__ w_hh,
                        const float* __restrict__ b_ih, const float* __restrict__ b_hh,
                        const float* __restrict__ w_fc, const float* __restrict__ b_fc,
                        float* __restrict__ out) {
    __shared__ float h[8][128], c[8][128], g[8][512], xs[8][8];
    int tid = threadIdx.x;
    for (int i = tid; i < 8 * 128; i += 1024) { ((float*)h)[i] = 0.f; ((float*)c)[i] = 0.f; }
    __syncthreads();
    for (int t = 0; t < T_STEPS; t++) {
        if (tid < 64) xs[tid >> 3][tid & 7] = g_emb[t * 64 + tid];
        __syncthreads();
        #pragma unroll
        for (int task = tid; task < 4096; task += 1024) {
            int b = task >> 9, row = task & 511;
            float acc = b_ih[row] + b_hh[row];
            const float* wi = w_ih + row * 8;
            #pragma unroll
            for (int k = 0; k < 8; k++) acc += xs[b][k] * wi[k];
            const float4* wh = (const float4*)(w_hh + row * 128);
            const float4* hb = (const float4*)h[b];
            #pragma unroll 8
            for (int j = 0; j < 32; j++) {
                float4 w4 = wh[j], h4 = hb[j];
                acc = fmaf(w4.x, h4.x, acc); acc = fmaf(w4.y, h4.y, acc);
                acc = fmaf(w4.z, h4.z, acc); acc = fmaf(w4.w, h4.w, acc);
            }
            g[b][row] = acc;
        }
        __syncthreads();
        if (tid < 1024) {
            int b = tid >> 7, u = tid & 127;
            float ig = sigmoidf(g[b][u]);
            float fg = sigmoidf(g[b][128 + u]);
            float gg = tanhf(g[b][256 + u]);
            float og = sigmoidf(g[b][384 + u]);
            float cn = fg * c[b][u] + ig * gg;
            c[b][u] = cn;
            h[b][u] = og * tanhf(cn);
        }
        __syncthreads();
    }
    if (tid < 16) {
        int b = tid >> 1, o = tid & 1;
        float acc = b_fc[o];
        const float* w = w_fc + o * 128;
        #pragma unroll 8
        for (int j = 0; j < 128; j++) acc += h[b][j] * w[j];
        out[b * 2 + o] = acc;
    }
}

// ---------------- host launch ----------------
extern "C" void kernel_launch(void* const* d_in, const int* in_sizes, int n_in,
                              void* d_out, int out_size) {
    const float *x_seq = 0, *W1 = 0, *as1 = 0, *ad1 = 0, *b1 = 0;
    const float *W2 = 0, *as2 = 0, *ad2 = 0, *b2 = 0;
    const float *W3 = 0, *as3 = 0, *ad3 = 0, *b3 = 0;
    const float *W4 = 0, *as4 = 0, *ad4 = 0, *b4 = 0;
    const float *w_ih = 0, *w_hh = 0, *b_ih = 0, *b_hh = 0, *w_fc = 0, *b_fc = 0;
    const int *edge = 0;
    int c1024 = 0, c512 = 0, c256 = 0, c128 = 0, c8 = 0;
    for (int i = 0; i < n_in; i++) {
        const float* p = (const float*)d_in[i];
        switch (in_sizes[i]) {
            case 172800: x_seq = p; break;
            case 276480: edge = (const int*)p; break;
            case 8640:   break;
            case 131072: W2 = p; break;
            case 65536:  w_hh = p; break;
            case 32768:  W3 = p; break;
            case 4096:   w_ih = p; break;
            case 1024:   { if (c1024++ == 0) W1 = p; else W4 = p; } break;
            case 512: { int k = c512++;
                if (k == 0) as1 = p; else if (k == 1) ad1 = p; else if (k == 2) b1 = p;
                else if (k == 3) b_ih = p; else b_hh = p; } break;
            case 256: { int k = c256++;
                if (k == 0) as2 = p; else if (k == 1) ad2 = p; else if (k == 2) b2 = p;
                else w_fc = p; } break;
            case 128: { int k = c128++;
                if (k == 0) as3 = p; else if (k == 1) ad3 = p; else b3 = p; } break;
            case 8: { int k = c8++;
                if (k == 0) as4 = p; else if (k == 1) ad4 = p; else b4 = p; } break;
            case 2: b_fc = p; break;
            default: break;
        }
    }
    const int* src = edge;

    float *bufA, *bufB;
    cudaGetSymbolAddress((void**)&bufA, g_bufA);
    cudaGetSymbolAddress((void**)&bufB, g_bufB);

    const int SM_L1   = (NPG * 2 + NPG * 8 * 2) * 4;             // 77760
    const int SM_F32  = (NPG * 32 + NPG * 2 + NPG * 17) * 4;     // 220320
    const int SM_F16  = (NPG * 16 + NPG * 2 + NPG * 17) * 4;     // 151200
    const int SM_F8   = (NPG * 8  + NPG * 2 + NPG * 17) * 4;     // 116640
    cudaFuncSetAttribute(l1_fused, cudaFuncAttributeMaxDynamicSharedMemorySize, SM_L1);
    cudaFuncSetAttribute(fused_gat<8, 32>, cudaFuncAttributeMaxDynamicSharedMemorySize, SM_F32);
    cudaFuncSetAttribute(fused_gat<8, 16>, cudaFuncAttributeMaxDynamicSharedMemorySize, SM_F16);
    cudaFuncSetAttribute(fused_gat<1, 8>,  cudaFuncAttributeMaxDynamicSharedMemorySize, SM_F8);

    prep_lsrc<<<(N_NODES * 16 + 255) / 256, 256>>>(src);
    uvec_l1<<<1, 32>>>(W1, as1, ad1);

    // layer 1 (fused) -> z
    l1_fused<<<T_STEPS * B_GR, 512, SM_L1>>>(x_seq);
    // layer 2 GEMM with fused L1 expansion: -> bufA [TN,256]
    l1gemm<<<dim3(2, TN / 128), 256>>>(W1, b1, W2, bufA, 256);
    fused_gat<8, 32><<<T_STEPS * B_GR * 8, 512, SM_F32>>>(bufA, as2, ad2, b2, bufB);

    // layer 3: [TN,256] @ [256,128] -> bufA
    gemm128<<<dim3(1, TN / 128), 256>>>(bufB, W3, bufA, 256, 128);
    fused_gat<8, 16><<<T_STEPS * B_GR * 8, 512, SM_F16>>>(bufA, as3, ad3, b3, bufB);

    // layer 4: [TN,128] @ [128,8] -> bufA
    gemm_l4<<<(TN * 8 + 255) / 256, 256>>>(bufB, W4, bufA);
    fused_gat<1, 8><<<T_STEPS * B_GR, 512, SM_F8>>>(bufA, as4, ad4, b4, bufB);

    pool_kernel<<<T_STEPS * B_GR, 256>>>(bufB);
    lstm_fc<<<1, 1024>>>(w_ih, w_hh, b_ih, b_hh, w_fc, b_fc, (float*)d_out);
}

// round 5
// speedup vs baseline: 2.4071x; 1.0412x over previous
#include <cuda_runtime.h>
#include <math.h>

#define T_STEPS 10
#define B_GR    8
#define NPG     1080
#define N_NODES 8640
#define TN      86400
#define DEG     16

// ---------------- scratch ----------------
__device__ float g_bufA[(size_t)TN * 256];
__device__ float g_bufB[(size_t)TN * 256];
__device__ float g_z[TN * 16];
__device__ float g_emb[T_STEPS * B_GR * 8];
__device__ float g_uv[32];
__device__ int   g_lsrc[N_NODES * 16];

// ---------------- fast exp for x <= 0 (FMA pipe only) ----------------
__device__ __forceinline__ float exp_neg(float x) {
    x = fmaxf(x, -87.0f);
    const float L2E = 1.4426950408889634f;
    float z = fmaf(x, L2E, 12582912.0f);
    int   ei = __float_as_int(z);
    float n = z - 12582912.0f;
    float f = fmaf(x, L2E, -n);
    float r = fmaf(1.5403530e-4f, f, 1.3333558e-3f);
    r = fmaf(r, f, 9.6181291e-3f);
    r = fmaf(r, f, 5.5504109e-2f);
    r = fmaf(r, f, 2.4022651e-1f);
    r = fmaf(r, f, 6.9314718e-1f);
    r = fmaf(r, f, 1.0f);
    float s = __int_as_float((ei + 127) << 23);
    return r * s;
}
__device__ __forceinline__ float elu_f(float v) { return v > 0.f ? v : exp_neg(v) - 1.f; }
__device__ __forceinline__ float lrelu(float e) { return e >= 0.f ? e : 0.2f * e; }

// ---------------- prep ----------------
__global__ void prep_lsrc(const int* __restrict__ src) {
    int i = blockIdx.x * blockDim.x + threadIdx.x;
    if (i >= N_NODES * 16) return;
    int b = i / (NPG * 16);
    g_lsrc[i] = src[i] - b * NPG;
}

__global__ void uvec_l1(const float* __restrict__ W1, const float* __restrict__ as1,
                        const float* __restrict__ ad1) {
    int tid = threadIdx.x;
    if (tid < 32) {
        int d = tid >> 4, h = (tid >> 1) & 7, f = tid & 1;
        const float* a = d ? ad1 : as1;
        float s = 0.f;
        #pragma unroll
        for (int c = 0; c < 64; c++) s += W1[f * 512 + h * 64 + c] * a[h * 64 + c];
        g_uv[tid] = s;
    }
}

// ---------------- layer 1 fully fused: x -> z[TN,16] ----------------
__global__ __launch_bounds__(512, 1)
void l1_fused(const float* __restrict__ x) {
    extern __shared__ float sm[];
    float* xs   = sm;                 // NPG*2
    float* es_s = xs + NPG * 2;       // NPG*8
    float* ed_s = es_s + NPG * 8;     // NPG*8
    __shared__ float uvS[32];
    int tb = blockIdx.x;
    int b = tb & 7, t = tb >> 3;
    int base = t * N_NODES + b * NPG;
    int tid = threadIdx.x;
    if (tid < 32) uvS[tid] = g_uv[tid];
    for (int i = tid; i < NPG * 2; i += blockDim.x) xs[i] = x[(size_t)base * 2 + i];
    __syncthreads();
    for (int task = tid; task < NPG * 8; task += blockDim.x) {
        int n = task >> 3, h = task & 7;
        float x0 = xs[n * 2], x1 = xs[n * 2 + 1];
        es_s[task] = fmaf(x0, uvS[h * 2], x1 * uvS[h * 2 + 1]);
        ed_s[task] = fmaf(x0, uvS[16 + h * 2], x1 * uvS[16 + h * 2 + 1]);
    }
    __syncthreads();
    for (int task = tid; task < NPG * 8; task += blockDim.x) {
        int n = task >> 3, h = task & 7;
        const int* ls = g_lsrc + ((size_t)b * NPG + n) * 16;
        float ed = ed_s[task];
        int idxs[16];
        float ev[17];
        float m = -1e30f;
        #pragma unroll
        for (int k = 0; k < 16; k++) {
            int s = ls[k];
            idxs[k] = s;
            float e = lrelu(es_s[s * 8 + h] + ed);
            ev[k] = e; m = fmaxf(m, e);
        }
        { float e = lrelu(es_s[task] + ed); ev[16] = e; m = fmaxf(m, e); }
        float ssum = 0.f;
        #pragma unroll
        for (int k = 0; k < 17; k++) { float v = exp_neg(ev[k] - m); ev[k] = v; ssum += v; }
        float inv = 1.f / (ssum + 1e-16f);
        float z0 = 0.f, z1 = 0.f;
        #pragma unroll
        for (int k = 0; k < 16; k++) {
            float a = ev[k] * inv;
            z0 = fmaf(a, xs[idxs[k] * 2], z0);
            z1 = fmaf(a, xs[idxs[k] * 2 + 1], z1);
        }
        {
            float a = ev[16] * inv;
            z0 = fmaf(a, xs[n * 2], z0);
            z1 = fmaf(a, xs[n * 2 + 1], z1);
        }
        *(float2*)&g_z[(size_t)(base + n) * 16 + h * 2] = make_float2(z0, z1);
    }
}

// ---------------- L2 GEMM, double-buffered, fused layer-1 expansion ----------------
__global__ __launch_bounds__(256, 2)
void l1gemm(const float* __restrict__ W1, const float* __restrict__ b1,
            const float* __restrict__ W, float* __restrict__ C, int Nc) {
    __shared__ float As[2][16][136];
    __shared__ float Ws[2][16][136];
    __shared__ float zs[128][16];
    __shared__ float W1s[1024];
    __shared__ float b1s[512];
    const int tid = threadIdx.x;
    const int tx = tid & 15, ty = tid >> 4;
    const int rb = blockIdx.y * 128, cb = blockIdx.x * 128;
    const int arow = tid >> 1, ap = tid & 1;
    const int wk = tid >> 5, wc = tid & 31;
    for (int i = tid; i < 1024; i += 256) W1s[i] = W1[i];
    for (int i = tid; i < 512; i += 256) b1s[i] = b1[i];
    for (int i = tid; i < 512; i += 256)
        *(float4*)&zs[i >> 2][(i & 3) * 4] = *(const float4*)(g_z + (size_t)(rb + (i >> 2)) * 16 + (i & 3) * 4);
    __syncthreads();
    float z0 = zs[arow][0], z1 = zs[arow][1];  // placeholder init (reset per k)
    // prologue: fill buffer 0 for k0 = 0
    {
        int kk = ap * 8, h = kk >> 6;
        float za = zs[arow][h * 2], zb = zs[arow][h * 2 + 1];
        #pragma unroll
        for (int j = 0; j < 8; j++) {
            int k = kk + j;
            As[0][ap * 8 + j][arow] = elu_f(fmaf(za, W1s[k], fmaf(zb, W1s[512 + k], b1s[k])));
        }
        *(float4*)&Ws[0][wk][wc * 4]     = *(const float4*)(W + (size_t)wk * Nc + cb + wc * 4);
        *(float4*)&Ws[0][wk + 8][wc * 4] = *(const float4*)(W + (size_t)(wk + 8) * Nc + cb + wc * 4);
    }
    __syncthreads();
    float acc[8][8] = {};
    for (int k0 = 0; k0 < 512; k0 += 16) {
        int p = (k0 >> 4) & 1;
        float av[8];
        float4 wv0, wv1;
        bool more = (k0 + 16) < 512;
        if (more) {
            int kk = k0 + 16 + ap * 8, h = kk >> 6;
            float za = zs[arow][h * 2], zb = zs[arow][h * 2 + 1];
            #pragma unroll
            for (int j = 0; j < 8; j++) {
                int k = kk + j;
                av[j] = elu_f(fmaf(za, W1s[k], fmaf(zb, W1s[512 + k], b1s[k])));
            }
            wv0 = *(const float4*)(W + (size_t)(k0 + 16 + wk) * Nc + cb + wc * 4);
            wv1 = *(const float4*)(W + (size_t)(k0 + 16 + wk + 8) * Nc + cb + wc * 4);
        }
        #pragma unroll
        for (int k = 0; k < 16; k++) {
            float4 a0 = *(const float4*)&As[p][k][ty * 4];
            float4 a1 = *(const float4*)&As[p][k][64 + ty * 4];
            float4 b0 = *(const float4*)&Ws[p][k][tx * 4];
            float4 b1v = *(const float4*)&Ws[p][k][64 + tx * 4];
            float a[8] = {a0.x, a0.y, a0.z, a0.w, a1.x, a1.y, a1.z, a1.w};
            float bv[8] = {b0.x, b0.y, b0.z, b0.w, b1v.x, b1v.y, b1v.z, b1v.w};
            #pragma unroll
            for (int i = 0; i < 8; i++)
                #pragma unroll
                for (int j = 0; j < 8; j++)
                    acc[i][j] = fmaf(a[i], bv[j], acc[i][j]);
        }
        if (more) {
            int q = p ^ 1;
            #pragma unroll
            for (int j = 0; j < 8; j++) As[q][ap * 8 + j][arow] = av[j];
            *(float4*)&Ws[q][wk][wc * 4] = wv0;
            *(float4*)&Ws[q][wk + 8][wc * 4] = wv1;
        }
        __syncthreads();
    }
    (void)z0; (void)z1;
    #pragma unroll
    for (int i = 0; i < 8; i++) {
        int r = rb + ((i < 4) ? (ty * 4 + i) : (64 + ty * 4 + i - 4));
        *(float4*)(C + (size_t)r * Nc + cb + tx * 4) = make_float4(acc[i][0], acc[i][1], acc[i][2], acc[i][3]);
        *(float4*)(C + (size_t)r * Nc + cb + 64 + tx * 4) = make_float4(acc[i][4], acc[i][5], acc[i][6], acc[i][7]);
    }
}

// ---------------- plain 128x128 fp32 GEMM, double-buffered (layer 3) ----------------
__global__ __launch_bounds__(256, 2)
void gemm128(const float* __restrict__ A, const float* __restrict__ W,
             float* __restrict__ C, int K, int Nc) {
    __shared__ float As[2][16][136];
    __shared__ float Ws[2][16][136];
    const int tid = threadIdx.x;
    const int tx = tid & 15, ty = tid >> 4;
    const int rb = blockIdx.y * 128, cb = blockIdx.x * 128;
    const int arow = tid >> 1, ap = tid & 1;
    const int wk = tid >> 5, wc = tid & 31;
    {
        const float* abase = A + (size_t)(rb + arow) * K + ap * 8;
        float4 av0 = *(const float4*)(abase);
        float4 av1 = *(const float4*)(abase + 4);
        As[0][ap * 8 + 0][arow] = av0.x; As[0][ap * 8 + 1][arow] = av0.y;
        As[0][ap * 8 + 2][arow] = av0.z; As[0][ap * 8 + 3][arow] = av0.w;
        As[0][ap * 8 + 4][arow] = av1.x; As[0][ap * 8 + 5][arow] = av1.y;
        As[0][ap * 8 + 6][arow] = av1.z; As[0][ap * 8 + 7][arow] = av1.w;
        *(float4*)&Ws[0][wk][wc * 4]     = *(const float4*)(W + (size_t)wk * Nc + cb + wc * 4);
        *(float4*)&Ws[0][wk + 8][wc * 4] = *(const float4*)(W + (size_t)(wk + 8) * Nc + cb + wc * 4);
    }
    __syncthreads();
    float acc[8][8] = {};
    for (int k0 = 0; k0 < K; k0 += 16) {
        int p = (k0 >> 4) & 1;
        float4 av0, av1, wv0, wv1;
        bool more = (k0 + 16) < K;
        if (more) {
            const float* abase = A + (size_t)(rb + arow) * K + k0 + 16 + ap * 8;
            av0 = *(const float4*)(abase);
            av1 = *(const float4*)(abase + 4);
            wv0 = *(const float4*)(W + (size_t)(k0 + 16 + wk) * Nc + cb + wc * 4);
            wv1 = *(const float4*)(W + (size_t)(k0 + 16 + wk + 8) * Nc + cb + wc * 4);
        }
        #pragma unroll
        for (int k = 0; k < 16; k++) {
            float4 a0 = *(const float4*)&As[p][k][ty * 4];
            float4 a1 = *(const float4*)&As[p][k][64 + ty * 4];
            float4 b0 = *(const float4*)&Ws[p][k][tx * 4];
            float4 b1 = *(const float4*)&Ws[p][k][64 + tx * 4];
            float a[8] = {a0.x, a0.y, a0.z, a0.w, a1.x, a1.y, a1.z, a1.w};
            float bv[8] = {b0.x, b0.y, b0.z, b0.w, b1.x, b1.y, b1.z, b1.w};
            #pragma unroll
            for (int i = 0; i < 8; i++)
                #pragma unroll
                for (int j = 0; j < 8; j++)
                    acc[i][j] = fmaf(a[i], bv[j], acc[i][j]);
        }
        if (more) {
            int q = p ^ 1;
            As[q][ap * 8 + 0][arow] = av0.x; As[q][ap * 8 + 1][arow] = av0.y;
            As[q][ap * 8 + 2][arow] = av0.z; As[q][ap * 8 + 3][arow] = av0.w;
            As[q][ap * 8 + 4][arow] = av1.x; As[q][ap * 8 + 5][arow] = av1.y;
            As[q][ap * 8 + 6][arow] = av1.z; As[q][ap * 8 + 7][arow] = av1.w;
            *(float4*)&Ws[q][wk][wc * 4] = wv0;
            *(float4*)&Ws[q][wk + 8][wc * 4] = wv1;
        }
        __syncthreads();
    }
    #pragma unroll
    for (int i = 0; i < 8; i++) {
        int r = rb + ((i < 4) ? (ty * 4 + i) : (64 + ty * 4 + i - 4));
        *(float4*)(C + (size_t)r * Nc + cb + tx * 4) = make_float4(acc[i][0], acc[i][1], acc[i][2], acc[i][3]);
        *(float4*)(C + (size_t)r * Nc + cb + 64 + tx * 4) = make_float4(acc[i][4], acc[i][5], acc[i][6], acc[i][7]);
    }
}

// ---------------- L4 GEMM ----------------
__global__ void gemm_l4(const float* __restrict__ X, const float* __restrict__ W4,
                        float* __restrict__ Y) {
    __shared__ float w[1024];
    int tid = threadIdx.x;
    for (int i = tid; i < 1024; i += blockDim.x) w[i] = W4[i];
    __syncthreads();
    int idx = blockIdx.x * blockDim.x + tid;
    if (idx >= TN * 8) return;
    int row = idx >> 3, j = idx & 7;
    const float4* xr = (const float4*)(X + (size_t)row * 128);
    float acc = 0.f;
    #pragma unroll 8
    for (int k = 0; k < 32; k++) {
        float4 v = xr[k];
        acc = fmaf(v.x, w[(k * 4 + 0) * 8 + j], acc);
        acc = fmaf(v.y, w[(k * 4 + 1) * 8 + j], acc);
        acc = fmaf(v.z, w[(k * 4 + 2) * 8 + j], acc);
        acc = fmaf(v.w, w[(k * 4 + 3) * 8 + j], acc);
    }
    Y[idx] = acc;
}

// ---------------- fully fused GAT, 1024 threads ----------------
template<int H, int C>
__global__ __launch_bounds__(1024, 1)
void fused_gat(const float* __restrict__ Y, const float* __restrict__ as_,
               const float* __restrict__ ad_, const float* __restrict__ bias,
               float* __restrict__ Xout) {
    extern __shared__ float sm[];
    constexpr int HC = H * C;
    constexpr int Q = C / 4;
    float* tile   = sm;                  // NPG*C
    float* es_s   = tile + NPG * C;      // NPG
    float* ed_s   = es_s + NPG;          // NPG
    float* alphaS = ed_s + NPG;          // NPG*17
    __shared__ float as_s[C], ad_s[C], bi_s[C];
    int blk = blockIdx.x;
    int h = (H == 1) ? 0 : (blk % H);
    int tb = (H == 1) ? blk : (blk / H);
    int b = tb % B_GR;
    int t = tb / B_GR;
    int base = t * N_NODES + b * NPG;
    int tid = threadIdx.x;
    if (tid < C) { as_s[tid] = as_[h * C + tid]; ad_s[tid] = ad_[h * C + tid]; bi_s[tid] = bias[h * C + tid]; }
    for (int i = tid; i < NPG * Q; i += blockDim.x) {
        int n = i / Q, q = i % Q;
        *(float4*)&tile[n * C + q * 4] =
            *(const float4*)(Y + (size_t)(base + n) * HC + h * C + q * 4);
    }
    __syncthreads();
    // phase 1: es/ed per node (lane-rotated)
    for (int n = tid; n < NPG; n += blockDim.x) {
        const float* tn = tile + n * C;
        int rot = tid & (Q - 1);
        float se = 0.f, de = 0.f;
        #pragma unroll
        for (int jj = 0; jj < Q; jj++) {
            int q = (jj + rot) & (Q - 1);
            float4 v = *(const float4*)&tn[q * 4];
            float4 a = *(const float4*)&as_s[q * 4];
            float4 d = *(const float4*)&ad_s[q * 4];
            se = fmaf(v.x, a.x, fmaf(v.y, a.y, fmaf(v.z, a.z, fmaf(v.w, a.w, se))));
            de = fmaf(v.x, d.x, fmaf(v.y, d.y, fmaf(v.z, d.z, fmaf(v.w, d.w, de))));
        }
        es_s[n] = se; ed_s[n] = de;
    }
    __syncthreads();
    // phase 2: two-pass softmax (low register footprint)
    for (int n = tid; n < NPG; n += blockDim.x) {
        const int4* ls4 = (const int4*)(g_lsrc + ((size_t)b * NPG + n) * 16);
        int4 i0 = ls4[0], i1 = ls4[1], i2 = ls4[2], i3 = ls4[3];
        float ed = ed_s[n];
        float m = lrelu(es_s[n] + ed);
        m = fmaxf(m, lrelu(es_s[i0.x] + ed)); m = fmaxf(m, lrelu(es_s[i0.y] + ed));
        m = fmaxf(m, lrelu(es_s[i0.z] + ed)); m = fmaxf(m, lrelu(es_s[i0.w] + ed));
        m = fmaxf(m, lrelu(es_s[i1.x] + ed)); m = fmaxf(m, lrelu(es_s[i1.y] + ed));
        m = fmaxf(m, lrelu(es_s[i1.z] + ed)); m = fmaxf(m, lrelu(es_s[i1.w] + ed));
        m = fmaxf(m, lrelu(es_s[i2.x] + ed)); m = fmaxf(m, lrelu(es_s[i2.y] + ed));
        m = fmaxf(m, lrelu(es_s[i2.z] + ed)); m = fmaxf(m, lrelu(es_s[i2.w] + ed));
        m = fmaxf(m, lrelu(es_s[i3.x] + ed)); m = fmaxf(m, lrelu(es_s[i3.y] + ed));
        m = fmaxf(m, lrelu(es_s[i3.z] + ed)); m = fmaxf(m, lrelu(es_s[i3.w] + ed));
        float* ap = alphaS + n * 17;
        float ssum = 0.f;
        float v;
        v = exp_neg(lrelu(es_s[i0.x] + ed) - m); ap[0]  = v; ssum += v;
        v = exp_neg(lrelu(es_s[i0.y] + ed) - m); ap[1]  = v; ssum += v;
        v = exp_neg(lrelu(es_s[i0.z] + ed) - m); ap[2]  = v; ssum += v;
        v = exp_neg(lrelu(es_s[i0.w] + ed) - m); ap[3]  = v; ssum += v;
        v = exp_neg(lrelu(es_s[i1.x] + ed) - m); ap[4]  = v; ssum += v;
        v = exp_neg(lrelu(es_s[i1.y] + ed) - m); ap[5]  = v; ssum += v;
        v = exp_neg(lrelu(es_s[i1.z] + ed) - m); ap[6]  = v; ssum += v;
        v = exp_neg(lrelu(es_s[i1.w] + ed) - m); ap[7]  = v; ssum += v;
        v = exp_neg(lrelu(es_s[i2.x] + ed) - m); ap[8]  = v; ssum += v;
        v = exp_neg(lrelu(es_s[i2.y] + ed) - m); ap[9]  = v; ssum += v;
        v = exp_neg(lrelu(es_s[i2.z] + ed) - m); ap[10] = v; ssum += v;
        v = exp_neg(lrelu(es_s[i2.w] + ed) - m); ap[11] = v; ssum += v;
        v = exp_neg(lrelu(es_s[i3.x] + ed) - m); ap[12] = v; ssum += v;
        v = exp_neg(lrelu(es_s[i3.y] + ed) - m); ap[13] = v; ssum += v;
        v = exp_neg(lrelu(es_s[i3.z] + ed) - m); ap[14] = v; ssum += v;
        v = exp_neg(lrelu(es_s[i3.w] + ed) - m); ap[15] = v; ssum += v;
        v = exp_neg(lrelu(es_s[n]    + ed) - m); ap[16] = v; ssum += v;
        float inv = 1.f / (ssum + 1e-16f);
        #pragma unroll
        for (int k = 0; k < 17; k++) ap[k] *= inv;
    }
    __syncthreads();
    // phase 3: aggregate + bias + ELU (conflict-free mapping)
    const int* lg = g_lsrc + (size_t)b * NPG * 16;
    for (int task = tid; task < NPG * Q; task += blockDim.x) {
        int n = task / Q, q = task % Q;
        const float* ap = alphaS + n * 17;
        float4 acc = make_float4(0.f, 0.f, 0.f, 0.f);
        #pragma unroll
        for (int k = 0; k < 16; k++) {
            int idx = lg[n * 16 + k];
            float a = ap[k];
            float4 v = *(const float4*)&tile[idx * C + q * 4];
            acc.x = fmaf(a, v.x, acc.x); acc.y = fmaf(a, v.y, acc.y);
            acc.z = fmaf(a, v.z, acc.z); acc.w = fmaf(a, v.w, acc.w);
        }
        {
            float a = ap[16];
            float4 v = *(const float4*)&tile[n * C + q * 4];
            acc.x = fmaf(a, v.x, acc.x); acc.y = fmaf(a, v.y, acc.y);
            acc.z = fmaf(a, v.z, acc.z); acc.w = fmaf(a, v.w, acc.w);
        }
        float4 o;
        o.x = elu_f(acc.x + bi_s[q * 4 + 0]); o.y = elu_f(acc.y + bi_s[q * 4 + 1]);
        o.z = elu_f(acc.z + bi_s[q * 4 + 2]); o.w = elu_f(acc.w + bi_s[q * 4 + 3]);
        *(float4*)(Xout + (size_t)(base + n) * HC + h * C + q * 4) = o;
    }
}

// ---------------- mean pool ----------------
__global__ void pool_kernel(const float* __restrict__ X4) {
    int tb = blockIdx.x;
    int t = tb / B_GR, b = tb % B_GR;
    int tid = threadIdx.x;
    float acc[8] = {};
    for (int nn = tid; nn < NPG; nn += blockDim.x) {
        const float* p = X4 + ((size_t)(t * N_NODES + b * NPG + nn)) * 8;
        #pragma unroll
        for (int f = 0; f < 8; f++) acc[f] += p[f];
    }
    __shared__ float s[8];
    if (tid < 8) s[tid] = 0.f;
    __syncthreads();
    #pragma unroll
    for (int f = 0; f < 8; f++) atomicAdd(&s[f], acc[f]);
    __syncthreads();
    if (tid < 8) g_emb[tb * 8 + tid] = s[tid] * (1.0f / (float)NPG);
}

// ---------------- LSTM + FC ----------------
__device__ __forceinline__ float sigmoidf(float x) { return 1.f / (1.f + expf(-x)); }

__global__ void lstm_fc(const float* __restrict__ w_ih, const float* __restrict__ w_hh,
                        const float* __restrict__ b_ih, const float* __restrict__ b_hh,
                        const float* __restrict__ w_fc, const float* __restrict__ b_fc,
                        float* __restrict__ out) {
    __shared__ float h[8][128], c[8][128], g[8][512], xs[8][8];
    int tid = threadIdx.x;
    for (int i = tid; i < 8 * 128; i += 1024) { ((float*)h)[i] = 0.f; ((float*)c)[i] = 0.f; }
    __syncthreads();
    for (int t = 0; t < T_STEPS; t++) {
        if (tid < 64) xs[tid >> 3][tid & 7] = g_emb[t * 64 + tid];
        __syncthreads();
        #pragma unroll
        for (int task = tid; task < 4096; task += 1024) {
            int b = task >> 9, row = task & 511;
            float acc = b_ih[row] + b_hh[row];
            const float* wi = w_ih + row * 8;
            #pragma unroll
            for (int k = 0; k < 8; k++) acc += xs[b][k] * wi[k];
            const float4* wh = (const float4*)(w_hh + row * 128);
            const float4* hb = (const float4*)h[b];
            #pragma unroll 8
            for (int j = 0; j < 32; j++) {
                float4 w4 = wh[j], h4 = hb[j];
                acc = fmaf(w4.x, h4.x, acc); acc = fmaf(w4.y, h4.y, acc);
                acc = fmaf(w4.z, h4.z, acc); acc = fmaf(w4.w, h4.w, acc);
            }
            g[b][row] = acc;
        }
        __syncthreads();
        if (tid < 1024) {
            int b = tid >> 7, u = tid & 127;
            float ig = sigmoidf(g[b][u]);
            float fg = sigmoidf(g[b][128 + u]);
            float gg = tanhf(g[b][256 + u]);
            float og = sigmoidf(g[b][384 + u]);
            float cn = fg * c[b][u] + ig * gg;
            c[b][u] = cn;
            h[b][u] = og * tanhf(cn);
        }
        __syncthreads();
    }
    if (tid < 16) {
        int b = tid >> 1, o = tid & 1;
        float acc = b_fc[o];
        const float* w = w_fc + o * 128;
        #pragma unroll 8
        for (int j = 0; j < 128; j++) acc += h[b][j] * w[j];
        out[b * 2 + o] = acc;
    }
}

// ---------------- host launch ----------------
extern "C" void kernel_launch(void* const* d_in, const int* in_sizes, int n_in,
                              void* d_out, int out_size) {
    const float *x_seq = 0, *W1 = 0, *as1 = 0, *ad1 = 0, *b1 = 0;
    const float *W2 = 0, *as2 = 0, *ad2 = 0, *b2 = 0;
    const float *W3 = 0, *as3 = 0, *ad3 = 0, *b3 = 0;
    const float *W4 = 0, *as4 = 0, *ad4 = 0, *b4 = 0;
    const float *w_ih = 0, *w_hh = 0, *b_ih = 0, *b_hh = 0, *w_fc = 0, *b_fc = 0;
    const int *edge = 0;
    int c1024 = 0, c512 = 0, c256 = 0, c128 = 0, c8 = 0;
    for (int i = 0; i < n_in; i++) {
        const float* p = (const float*)d_in[i];
        switch (in_sizes[i]) {
            case 172800: x_seq = p; break;
            case 276480: edge = (const int*)p; break;
            case 8640:   break;
            case 131072: W2 = p; break;
            case 65536:  w_hh = p; break;
            case 32768:  W3 = p; break;
            case 4096:   w_ih = p; break;
            case 1024:   { if (c1024++ == 0) W1 = p; else W4 = p; } break;
            case 512: { int k = c512++;
                if (k == 0) as1 = p; else if (k == 1) ad1 = p; else if (k == 2) b1 = p;
                else if (k == 3) b_ih = p; else b_hh = p; } break;
            case 256: { int k = c256++;
                if (k == 0) as2 = p; else if (k == 1) ad2 = p; else if (k == 2) b2 = p;
                else w_fc = p; } break;
            case 128: { int k = c128++;
                if (k == 0) as3 = p; else if (k == 1) ad3 = p; else b3 = p; } break;
            case 8: { int k = c8++;
                if (k == 0) as4 = p; else if (k == 1) ad4 = p; else b4 = p; } break;
            case 2: b_fc = p; break;
            default: break;
        }
    }
    const int* src = edge;

    float *bufA, *bufB;
    cudaGetSymbolAddress((void**)&bufA, g_bufA);
    cudaGetSymbolAddress((void**)&bufB, g_bufB);

    const int SM_L1   = (NPG * 2 + NPG * 8 * 2) * 4;             // 77760
    const int SM_F32  = (NPG * 32 + NPG * 2 + NPG * 17) * 4;     // 220320
    const int SM_F16  = (NPG * 16 + NPG * 2 + NPG * 17) * 4;     // 151200
    const int SM_F8   = (NPG * 8  + NPG * 2 + NPG * 17) * 4;     // 116640
    cudaFuncSetAttribute(l1_fused, cudaFuncAttributeMaxDynamicSharedMemorySize, SM_L1);
    cudaFuncSetAttribute(fused_gat<8, 32>, cudaFuncAttributeMaxDynamicSharedMemorySize, SM_F32);
    cudaFuncSetAttribute(fused_gat<8, 16>, cudaFuncAttributeMaxDynamicSharedMemorySize, SM_F16);
    cudaFuncSetAttribute(fused_gat<1, 8>,  cudaFuncAttributeMaxDynamicSharedMemorySize, SM_F8);

    prep_lsrc<<<(N_NODES * 16 + 255) / 256, 256>>>(src);
    uvec_l1<<<1, 32>>>(W1, as1, ad1);

    l1_fused<<<T_STEPS * B_GR, 512, SM_L1>>>(x_seq);
    l1gemm<<<dim3(2, TN / 128), 256>>>(W1, b1, W2, bufA, 256);
    fused_gat<8, 32><<<T_STEPS * B_GR * 8, 1024, SM_F32>>>(bufA, as2, ad2, b2, bufB);

    gemm128<<<dim3(1, TN / 128), 256>>>(bufB, W3, bufA, 256, 128);
    fused_gat<8, 16><<<T_STEPS * B_GR * 8, 1024, SM_F16>>>(bufA, as3, ad3, b3, bufB);

    gemm_l4<<<(TN * 8 + 255) / 256, 256>>>(bufB, W4, bufA);
    fused_gat<1, 8><<<T_STEPS * B_GR, 1024, SM_F8>>>(bufA, as4, ad4, b4, bufB);

    pool_kernel<<<T_STEPS * B_GR, 256>>>(bufB);
    lstm_fc<<<1, 1024>>>(w_ih, w_hh, b_ih, b_hh, w_fc, b_fc, (float*)d_out);
}